// round 1
// baseline (speedup 1.0000x reference)
#include <cuda_runtime.h>
#include <math.h>

// Problem shape (from reference): B=1024, D=256, N=100000 (runtime from in_sizes)
#define B_DIM 1024
#define D_DIM 256
#define MAXN  100352            // capacity (multiple of 128)
#define MAXSPLIT 64             // capacity for N-splits of 2048

// ---------------- scratch (device globals; no allocation in kernel_launch) ---
__device__ float g_proj[B_DIM * D_DIM];                    // 1 MB
__device__ float g_bias[MAXN];                             // 0.4 MB
__device__ float g_L[B_DIM];                               // logsumexp per row
__device__ float g_z[(size_t)B_DIM * MAXN];                // ~411 MB logits
__device__ float g_part[(size_t)MAXSPLIT * B_DIM * D_DIM]; // 67 MB split partials
__device__ int   g_cmax[MAXN];                             // col-max(w) as float bits (>=0)
__device__ int   g_logdmax;                                // max log1p(depth) as float bits

// ---------------- init: zero atomically-reduced scratch ----------------------
__global__ void init_kernel(int Nn) {
    int i = blockIdx.x * blockDim.x + threadIdx.x;
    if (i < Nn) g_cmax[i] = 0;
    if (i == 0) g_logdmax = 0;
}

// ---------------- projection: proj[b][j] = sum_d state[b][d] * W[j][d] -------
__global__ void proj_kernel(const float* __restrict__ state,
                            const float* __restrict__ W) {
    __shared__ float s[D_DIM];
    int b = blockIdx.x, j = threadIdx.x;
    s[j] = state[b * D_DIM + j];
    __syncthreads();
    const float* wr = W + j * D_DIM;
    float acc = 0.f;
#pragma unroll 16
    for (int d = 0; d < D_DIM; ++d) acc = fmaf(s[d], wr[d], acc);
    g_proj[b * D_DIM + j] = acc;
}

// ---------------- bias = log(clip(depth)) + log(clip(gate)); max log1p(depth)
__global__ void bias_kernel(const float* __restrict__ depths,
                            const float* __restrict__ gate, int Nn) {
    int i = blockIdx.x * 256 + threadIdx.x;
    float lv = 0.f;
    if (i < Nn) {
        float d = depths[i], g = gate[i];
        g_bias[i] = logf(fmaxf(d, 1e-8f)) + logf(fmaxf(g, 1e-8f));
        lv = log1pf(d);
    }
    __shared__ float red[256];
    red[threadIdx.x] = lv;
    __syncthreads();
#pragma unroll
    for (int o = 128; o > 0; o >>= 1) {
        if (threadIdx.x < o) red[threadIdx.x] = fmaxf(red[threadIdx.x], red[threadIdx.x + o]);
        __syncthreads();
    }
    if (threadIdx.x == 0) atomicMax(&g_logdmax, __float_as_int(red[0]));
}

// ---------------- SGEMM1: z[m][n] = proj[m][:] . pat[n][:] + bias[n] ---------
// Tile 128x128, K-step 8, 256 threads, 8x8 micro-tile, double-buffered smem.
__global__ __launch_bounds__(256) void gemm_z_kernel(const float* __restrict__ pat,
                                                     int Nn) {
    __shared__ float As[2][8][128];
    __shared__ float Bs[2][8][128];
    const int m0 = blockIdx.x * 128;         // 8 m-tiles
    const int n0 = blockIdx.y * 128;         // ceil(Nn/128) n-tiles
    const int tid = threadIdx.x;
    const int lrow = tid >> 1;               // 0..127
    const int lk   = (tid & 1) * 4;          // 0 or 4
    const int tx = tid & 15, ty = tid >> 4;

    const float* aptr = g_proj + (m0 + lrow) * D_DIM + lk;
    const long  brow  = (long)n0 + lrow;
    const float* bptr = pat + brow * D_DIM + lk;
    const bool  bval  = brow < Nn;

    float acc0[4][4], acc1[4][4], acc2[4][4], acc3[4][4];
#pragma unroll
    for (int i = 0; i < 4; ++i)
#pragma unroll
        for (int j = 0; j < 4; ++j) { acc0[i][j] = acc1[i][j] = acc2[i][j] = acc3[i][j] = 0.f; }

    float4 ar = *(const float4*)aptr;
    float4 br = bval ? *(const float4*)bptr : make_float4(0.f, 0.f, 0.f, 0.f);
    int buf = 0;
    As[0][lk + 0][lrow] = ar.x; As[0][lk + 1][lrow] = ar.y;
    As[0][lk + 2][lrow] = ar.z; As[0][lk + 3][lrow] = ar.w;
    Bs[0][lk + 0][lrow] = br.x; Bs[0][lk + 1][lrow] = br.y;
    Bs[0][lk + 2][lrow] = br.z; Bs[0][lk + 3][lrow] = br.w;
    __syncthreads();

    for (int k0 = 0; k0 < D_DIM; k0 += 8) {
        const bool more = (k0 + 8) < D_DIM;
        if (more) {
            ar = *(const float4*)(aptr + k0 + 8);
            br = bval ? *(const float4*)(bptr + k0 + 8) : make_float4(0.f, 0.f, 0.f, 0.f);
        }
#pragma unroll
        for (int k = 0; k < 8; ++k) {
            float af0[4], af1[4], bf0[4], bf1[4];
            *(float4*)af0 = *(const float4*)&As[buf][k][ty * 4];
            *(float4*)af1 = *(const float4*)&As[buf][k][64 + ty * 4];
            *(float4*)bf0 = *(const float4*)&Bs[buf][k][tx * 4];
            *(float4*)bf1 = *(const float4*)&Bs[buf][k][64 + tx * 4];
#pragma unroll
            for (int mi = 0; mi < 4; ++mi)
#pragma unroll
                for (int ni = 0; ni < 4; ++ni) {
                    acc0[mi][ni] = fmaf(af0[mi], bf0[ni], acc0[mi][ni]);
                    acc1[mi][ni] = fmaf(af0[mi], bf1[ni], acc1[mi][ni]);
                    acc2[mi][ni] = fmaf(af1[mi], bf0[ni], acc2[mi][ni]);
                    acc3[mi][ni] = fmaf(af1[mi], bf1[ni], acc3[mi][ni]);
                }
        }
        if (more) {
            As[buf ^ 1][lk + 0][lrow] = ar.x; As[buf ^ 1][lk + 1][lrow] = ar.y;
            As[buf ^ 1][lk + 2][lrow] = ar.z; As[buf ^ 1][lk + 3][lrow] = ar.w;
            Bs[buf ^ 1][lk + 0][lrow] = br.x; Bs[buf ^ 1][lk + 1][lrow] = br.y;
            Bs[buf ^ 1][lk + 2][lrow] = br.z; Bs[buf ^ 1][lk + 3][lrow] = br.w;
        }
        __syncthreads();
        buf ^= 1;
    }

    // epilogue: add bias, store z
    const bool vecOK = ((Nn & 3) == 0);
#pragma unroll
    for (int gm = 0; gm < 2; ++gm) {
#pragma unroll
        for (int mi = 0; mi < 4; ++mi) {
            const int m = m0 + gm * 64 + ty * 4 + mi;
#pragma unroll
            for (int gn = 0; gn < 2; ++gn) {
                const int c = gn * 64 + tx * 4;
                const long n = (long)n0 + c;
                float v[4];
#pragma unroll
                for (int ni = 0; ni < 4; ++ni)
                    v[ni] = (gm == 0) ? ((gn == 0) ? acc0[mi][ni] : acc1[mi][ni])
                                      : ((gn == 0) ? acc2[mi][ni] : acc3[mi][ni]);
                if (vecOK && (n + 4 <= Nn)) {
                    float4 b4 = *(const float4*)&g_bias[n];
                    float4 o  = make_float4(v[0] + b4.x, v[1] + b4.y, v[2] + b4.z, v[3] + b4.w);
                    *(float4*)&g_z[(long)m * Nn + n] = o;
                } else {
#pragma unroll
                    for (int ni = 0; ni < 4; ++ni)
                        if (n + ni < Nn) g_z[(long)m * Nn + n + ni] = v[ni] + g_bias[n + ni];
                }
            }
        }
    }
}

// ---------------- row logsumexp: L[b] = m + log(sum exp(z-m)) ----------------
__global__ void lse_kernel(int Nn) {
    const int b = blockIdx.x, tid = threadIdx.x;
    const float* zr = g_z + (long)b * Nn;
    float m = -INFINITY, s = 0.f;
    const int n4 = Nn >> 2;
    const float4* zr4 = (const float4*)zr;
    for (int i = tid; i < n4; i += 256) {
        float4 v = zr4[i];
        float mv = fmaxf(fmaxf(v.x, v.y), fmaxf(v.z, v.w));
        if (mv > m) { s *= expf(m - mv); m = mv; }
        s += expf(v.x - m) + expf(v.y - m) + expf(v.z - m) + expf(v.w - m);
    }
    for (int i = (n4 << 2) + tid; i < Nn; i += 256) {   // tail (Nn%4)
        float v = zr[i];
        if (v > m) { s *= expf(m - v); m = v; }
        s += expf(v - m);
    }
    __shared__ float sm[256], ss[256];
    sm[tid] = m; ss[tid] = s;
    __syncthreads();
#pragma unroll
    for (int o = 128; o > 0; o >>= 1) {
        if (tid < o) {
            float m2 = sm[tid + o], s2 = ss[tid + o];
            float M = fmaxf(sm[tid], m2);
            ss[tid] = ss[tid] * expf(sm[tid] - M) + s2 * expf(m2 - M);
            sm[tid] = M;
        }
        __syncthreads();
    }
    if (tid == 0) g_L[b] = sm[0] + logf(ss[0]);
}

// ---------------- SGEMM2: retrieved partials + column max of weights ---------
// CTA: 64 b-rows x one 2048-wide N chunk. Inner tile: 32 patterns.
__global__ __launch_bounds__(256) void out_gemm_kernel(const float* __restrict__ pat,
                                                       int Nn, int nsplit) {
    __shared__ float Ps[32][256];       // pattern tile [n][d]
    __shared__ float Ws[32][68];        // weights [n][b-in-tile], padded
    __shared__ float Ls[64];
    const int b0 = blockIdx.x * 64;       // 16 row tiles
    const int split = blockIdx.y;
    const int nstart = split * 2048;
    const int nend = min(nstart + 2048, Nn);
    const int tid = threadIdx.x;
    const int tx = tid & 15, ty = tid >> 4;

    if (tid < 64) Ls[tid] = g_L[b0 + tid];
    __syncthreads();

    float acc[4][4][4];                   // [row][colgroup][col]
#pragma unroll
    for (int a = 0; a < 4; ++a)
#pragma unroll
        for (int g = 0; g < 4; ++g)
#pragma unroll
            for (int c = 0; c < 4; ++c) acc[a][g][c] = 0.f;

    const bool vecOK = ((Nn & 3) == 0);

    for (int n0 = nstart; n0 < nend; n0 += 32) {
        __syncthreads();   // protect smem reuse from previous tile's readers
        // load pattern tile 32x256 (zero-fill past nend)
#pragma unroll
        for (int i = 0; i < 8; ++i) {
            int q = tid + i * 256;            // 0..2047
            int r = q >> 6;                   // 0..31
            int c = (q & 63) * 4;
            int n = n0 + r;
            float4 v = (n < nend) ? *(const float4*)&pat[(long)n * D_DIM + c]
                                  : make_float4(0.f, 0.f, 0.f, 0.f);
            *(float4*)&Ps[r][c] = v;
        }
        // load z tile 64x32, compute weights, store transposed to Ws
#pragma unroll
        for (int i = 0; i < 2; ++i) {
            int q = tid + i * 256;            // 0..511
            int r = q >> 3;                   // b-row in tile, 0..63
            int j = (q & 7) * 4;              // n-col in tile
            int n = n0 + j;
            float lb = Ls[r];
            float w0 = 0.f, w1 = 0.f, w2 = 0.f, w3 = 0.f;
            if (vecOK && (n + 4 <= nend)) {
                float4 z4 = *(const float4*)&g_z[(long)(b0 + r) * Nn + n];
                w0 = expf(z4.x - lb); w1 = expf(z4.y - lb);
                w2 = expf(z4.z - lb); w3 = expf(z4.w - lb);
            } else {
                if (n + 0 < nend) w0 = expf(g_z[(long)(b0 + r) * Nn + n + 0] - lb);
                if (n + 1 < nend) w1 = expf(g_z[(long)(b0 + r) * Nn + n + 1] - lb);
                if (n + 2 < nend) w2 = expf(g_z[(long)(b0 + r) * Nn + n + 2] - lb);
                if (n + 3 < nend) w3 = expf(g_z[(long)(b0 + r) * Nn + n + 3] - lb);
            }
            Ws[j + 0][r] = w0; Ws[j + 1][r] = w1;
            Ws[j + 2][r] = w2; Ws[j + 3][r] = w3;
        }
        __syncthreads();
        // column max over the 64 rows of this tile -> atomicMax
        if (tid < 128) {
            int j = tid >> 2;
            int qr = (tid & 3) * 16;
            float mx = 0.f;
#pragma unroll
            for (int r = 0; r < 16; ++r) mx = fmaxf(mx, Ws[j][qr + r]);
            mx = fmaxf(mx, __shfl_xor_sync(0xffffffffu, mx, 1));
            mx = fmaxf(mx, __shfl_xor_sync(0xffffffffu, mx, 2));
            if ((tid & 3) == 0 && (n0 + j) < nend)
                atomicMax(&g_cmax[n0 + j], __float_as_int(mx));
        }
        // accumulate retrieved: acc[r][c] += w[r][j] * Ps[j][c]
#pragma unroll
        for (int j = 0; j < 32; ++j) {
            float wv[4];
            *(float4*)wv = *(const float4*)&Ws[j][ty * 4];
#pragma unroll
            for (int g = 0; g < 4; ++g) {
                float pv[4];
                *(float4*)pv = *(const float4*)&Ps[j][g * 64 + tx * 4];
#pragma unroll
                for (int mi = 0; mi < 4; ++mi)
#pragma unroll
                    for (int ci = 0; ci < 4; ++ci)
                        acc[mi][g][ci] = fmaf(wv[mi], pv[ci], acc[mi][g][ci]);
            }
        }
    }
    // write split partials (deterministic reduction later)
    const long base = ((long)split * B_DIM + b0) * D_DIM;
#pragma unroll
    for (int mi = 0; mi < 4; ++mi) {
        int r = ty * 4 + mi;
#pragma unroll
        for (int g = 0; g < 4; ++g) {
            float4 o = make_float4(acc[mi][g][0], acc[mi][g][1], acc[mi][g][2], acc[mi][g][3]);
            *(float4*)&g_part[base + (long)r * D_DIM + g * 64 + tx * 4] = o;
        }
    }
}

// ---------------- reduce split partials into retrieved -----------------------
__global__ void reduce_ret_kernel(float* __restrict__ out, int nsplit) {
    int i = blockIdx.x * 256 + threadIdx.x;      // float4 index, 0..65535
    float4 s = make_float4(0.f, 0.f, 0.f, 0.f);
    for (int sp = 0; sp < nsplit; ++sp) {
        float4 v = *(const float4*)&g_part[(long)sp * (B_DIM * D_DIM) + (long)i * 4];
        s.x += v.x; s.y += v.y; s.z += v.z; s.w += v.w;
    }
    *(float4*)&out[(long)i * 4] = s;
}

// ---------------- final depth reinforcement ----------------------------------
__global__ void depths_kernel(const float* __restrict__ depths,
                              float* __restrict__ out, int Nn) {
    int i = blockIdx.x * 256 + threadIdx.x;
    if (i >= Nn) return;
    float d = depths[i];
    float maxw = __int_as_float(g_cmax[i]);
    float logd = log1pf(d);
    float dommax = fmaxf(__int_as_float(g_logdmax), 1e-8f);
    float dom = logd / dommax;
    float rate = 0.01f * (1.0f - 0.7f * dom);
    float nd = d + ((maxw > 0.1f) ? rate * maxw : 0.0f);
    out[B_DIM * D_DIM + i] = nd;
}

// ---------------- launch ------------------------------------------------------
extern "C" void kernel_launch(void* const* d_in, const int* in_sizes, int n_in,
                              void* d_out, int out_size) {
    const float* state   = (const float*)d_in[0];
    const float* W       = (const float*)d_in[1];
    const float* pat     = (const float*)d_in[2];
    const float* depths  = (const float*)d_in[3];
    const float* gate    = (const float*)d_in[4];
    float* out = (float*)d_out;
    const int Nn = in_sizes[3];

    const int nbN = (Nn + 255) / 256;
    init_kernel<<<nbN, 256>>>(Nn);
    proj_kernel<<<B_DIM, 256>>>(state, W);
    bias_kernel<<<nbN, 256>>>(depths, gate, Nn);

    const int ntiles = (Nn + 127) / 128;
    gemm_z_kernel<<<dim3(B_DIM / 128, ntiles), 256>>>(pat, Nn);

    lse_kernel<<<B_DIM, 256>>>(Nn);

    const int nsplit = (Nn + 2047) / 2048;
    out_gemm_kernel<<<dim3(B_DIM / 64, nsplit), 256>>>(pat, Nn, nsplit);

    reduce_ret_kernel<<<(B_DIM * D_DIM / 4) / 256, 256>>>(out, nsplit);
    depths_kernel<<<nbN, 256>>>(depths, out, Nn);
}

// round 2
// speedup vs baseline: 1.5173x; 1.5173x over previous
#include <cuda_runtime.h>
#include <math.h>

// Problem shape (from reference): B=1024, D=256, N=100000 (runtime from in_sizes)
#define B_DIM 1024
#define D_DIM 256
#define MAXN  100352            // capacity (multiple of 128)
#define MAXSPLIT 64             // capacity for N-splits of 2048

// ---------------- scratch (device globals; no allocation in kernel_launch) ---
__device__ float g_proj[B_DIM * D_DIM];                    // 1 MB
__device__ float g_bias[MAXN];                             // 0.4 MB
__device__ float g_L[B_DIM];                               // logsumexp per row
__device__ float g_z[(size_t)B_DIM * MAXN];                // ~411 MB logits
__device__ float g_part[(size_t)MAXSPLIT * B_DIM * D_DIM]; // 67 MB split partials
__device__ int   g_cmax[MAXN];                             // col-max(w) as float bits (>=0)
__device__ int   g_logdmax;                                // max log1p(depth) as float bits

// ---------------- init: zero atomically-reduced scratch ----------------------
__global__ void init_kernel(int Nn) {
    int i = blockIdx.x * blockDim.x + threadIdx.x;
    if (i < Nn) g_cmax[i] = 0;
    if (i == 0) g_logdmax = 0;
}

// ---------------- projection: proj[b][j] = sum_d state[b][d] * W[j][d] -------
__global__ void proj_kernel(const float* __restrict__ state,
                            const float* __restrict__ W) {
    __shared__ float s[D_DIM];
    int b = blockIdx.x, j = threadIdx.x;
    s[j] = state[b * D_DIM + j];
    __syncthreads();
    const float* wr = W + j * D_DIM;
    float acc = 0.f;
#pragma unroll 16
    for (int d = 0; d < D_DIM; ++d) acc = fmaf(s[d], wr[d], acc);
    g_proj[b * D_DIM + j] = acc;
}

// ---------------- bias = log(clip(depth)) + log(clip(gate)); max log1p(depth)
__global__ void bias_kernel(const float* __restrict__ depths,
                            const float* __restrict__ gate, int Nn) {
    int i = blockIdx.x * 256 + threadIdx.x;
    float lv = 0.f;
    if (i < Nn) {
        float d = depths[i], g = gate[i];
        g_bias[i] = logf(fmaxf(d, 1e-8f)) + logf(fmaxf(g, 1e-8f));
        lv = log1pf(d);
    }
    __shared__ float red[256];
    red[threadIdx.x] = lv;
    __syncthreads();
#pragma unroll
    for (int o = 128; o > 0; o >>= 1) {
        if (threadIdx.x < o) red[threadIdx.x] = fmaxf(red[threadIdx.x], red[threadIdx.x + o]);
        __syncthreads();
    }
    if (threadIdx.x == 0) atomicMax(&g_logdmax, __float_as_int(red[0]));
}

// ---------------- SGEMM1: z[m][n] = proj[m][:] . pat[n][:] + bias[n] ---------
// Tile 128x128, K-step 8, 256 threads, 8x8 micro-tile, double-buffered smem.
__global__ __launch_bounds__(256) void gemm_z_kernel(const float* __restrict__ pat,
                                                     int Nn) {
    __shared__ float As[2][8][128];
    __shared__ float Bs[2][8][128];
    const int m0 = blockIdx.x * 128;         // 8 m-tiles
    const int n0 = blockIdx.y * 128;         // ceil(Nn/128) n-tiles
    const int tid = threadIdx.x;
    const int lrow = tid >> 1;               // 0..127
    const int lk   = (tid & 1) * 4;          // 0 or 4
    const int tx = tid & 15, ty = tid >> 4;

    const float* aptr = g_proj + (m0 + lrow) * D_DIM + lk;
    const long  brow  = (long)n0 + lrow;
    const float* bptr = pat + brow * D_DIM + lk;
    const bool  bval  = brow < Nn;

    float acc0[4][4], acc1[4][4], acc2[4][4], acc3[4][4];
#pragma unroll
    for (int i = 0; i < 4; ++i)
#pragma unroll
        for (int j = 0; j < 4; ++j) { acc0[i][j] = acc1[i][j] = acc2[i][j] = acc3[i][j] = 0.f; }

    float4 ar = *(const float4*)aptr;
    float4 br = bval ? *(const float4*)bptr : make_float4(0.f, 0.f, 0.f, 0.f);
    int buf = 0;
    As[0][lk + 0][lrow] = ar.x; As[0][lk + 1][lrow] = ar.y;
    As[0][lk + 2][lrow] = ar.z; As[0][lk + 3][lrow] = ar.w;
    Bs[0][lk + 0][lrow] = br.x; Bs[0][lk + 1][lrow] = br.y;
    Bs[0][lk + 2][lrow] = br.z; Bs[0][lk + 3][lrow] = br.w;
    __syncthreads();

    for (int k0 = 0; k0 < D_DIM; k0 += 8) {
        const bool more = (k0 + 8) < D_DIM;
        if (more) {
            ar = *(const float4*)(aptr + k0 + 8);
            br = bval ? *(const float4*)(bptr + k0 + 8) : make_float4(0.f, 0.f, 0.f, 0.f);
        }
#pragma unroll
        for (int k = 0; k < 8; ++k) {
            float af0[4], af1[4], bf0[4], bf1[4];
            *(float4*)af0 = *(const float4*)&As[buf][k][ty * 4];
            *(float4*)af1 = *(const float4*)&As[buf][k][64 + ty * 4];
            *(float4*)bf0 = *(const float4*)&Bs[buf][k][tx * 4];
            *(float4*)bf1 = *(const float4*)&Bs[buf][k][64 + tx * 4];
#pragma unroll
            for (int mi = 0; mi < 4; ++mi)
#pragma unroll
                for (int ni = 0; ni < 4; ++ni) {
                    acc0[mi][ni] = fmaf(af0[mi], bf0[ni], acc0[mi][ni]);
                    acc1[mi][ni] = fmaf(af0[mi], bf1[ni], acc1[mi][ni]);
                    acc2[mi][ni] = fmaf(af1[mi], bf0[ni], acc2[mi][ni]);
                    acc3[mi][ni] = fmaf(af1[mi], bf1[ni], acc3[mi][ni]);
                }
        }
        if (more) {
            As[buf ^ 1][lk + 0][lrow] = ar.x; As[buf ^ 1][lk + 1][lrow] = ar.y;
            As[buf ^ 1][lk + 2][lrow] = ar.z; As[buf ^ 1][lk + 3][lrow] = ar.w;
            Bs[buf ^ 1][lk + 0][lrow] = br.x; Bs[buf ^ 1][lk + 1][lrow] = br.y;
            Bs[buf ^ 1][lk + 2][lrow] = br.z; Bs[buf ^ 1][lk + 3][lrow] = br.w;
        }
        __syncthreads();
        buf ^= 1;
    }

    // epilogue: add bias, store z
    const bool vecOK = ((Nn & 3) == 0);
#pragma unroll
    for (int gm = 0; gm < 2; ++gm) {
#pragma unroll
        for (int mi = 0; mi < 4; ++mi) {
            const int m = m0 + gm * 64 + ty * 4 + mi;
#pragma unroll
            for (int gn = 0; gn < 2; ++gn) {
                const int c = gn * 64 + tx * 4;
                const long n = (long)n0 + c;
                float v[4];
#pragma unroll
                for (int ni = 0; ni < 4; ++ni)
                    v[ni] = (gm == 0) ? ((gn == 0) ? acc0[mi][ni] : acc1[mi][ni])
                                      : ((gn == 0) ? acc2[mi][ni] : acc3[mi][ni]);
                if (vecOK && (n + 4 <= Nn)) {
                    float4 b4 = *(const float4*)&g_bias[n];
                    float4 o  = make_float4(v[0] + b4.x, v[1] + b4.y, v[2] + b4.z, v[3] + b4.w);
                    *(float4*)&g_z[(long)m * Nn + n] = o;
                } else {
#pragma unroll
                    for (int ni = 0; ni < 4; ++ni)
                        if (n + ni < Nn) g_z[(long)m * Nn + n + ni] = v[ni] + g_bias[n + ni];
                }
            }
        }
    }
}

// ---------------- row logsumexp: L[b] = m + log(sum exp(z-m)) ----------------
__global__ void lse_kernel(int Nn) {
    const int b = blockIdx.x, tid = threadIdx.x;
    const float* zr = g_z + (long)b * Nn;
    float m = -INFINITY, s = 0.f;
    const int n4 = Nn >> 2;
    const float4* zr4 = (const float4*)zr;
    for (int i = tid; i < n4; i += 256) {
        float4 v = zr4[i];
        float mv = fmaxf(fmaxf(v.x, v.y), fmaxf(v.z, v.w));
        if (mv > m) { s *= expf(m - mv); m = mv; }
        s += expf(v.x - m) + expf(v.y - m) + expf(v.z - m) + expf(v.w - m);
    }
    for (int i = (n4 << 2) + tid; i < Nn; i += 256) {   // tail (Nn%4)
        float v = zr[i];
        if (v > m) { s *= expf(m - v); m = v; }
        s += expf(v - m);
    }
    __shared__ float sm[256], ss[256];
    sm[tid] = m; ss[tid] = s;
    __syncthreads();
#pragma unroll
    for (int o = 128; o > 0; o >>= 1) {
        if (tid < o) {
            float m2 = sm[tid + o], s2 = ss[tid + o];
            float M = fmaxf(sm[tid], m2);
            ss[tid] = ss[tid] * expf(sm[tid] - M) + s2 * expf(m2 - M);
            sm[tid] = M;
        }
        __syncthreads();
    }
    if (tid == 0) g_L[b] = sm[0] + logf(ss[0]);
}

// ---------------- SGEMM2: retrieved partials + column max of weights ---------
// CTA: 64 b-rows x one 2048-wide N chunk. Inner tile: 32 patterns.
__global__ __launch_bounds__(256) void out_gemm_kernel(const float* __restrict__ pat,
                                                       int Nn, int nsplit) {
    __shared__ float Ps[32][256];       // pattern tile [n][d]
    __shared__ float Ws[32][68];        // weights [n][b-in-tile], padded
    __shared__ float Ls[64];
    const int b0 = blockIdx.x * 64;       // 16 row tiles
    const int split = blockIdx.y;
    const int nstart = split * 2048;
    const int nend = min(nstart + 2048, Nn);
    const int tid = threadIdx.x;
    const int tx = tid & 15, ty = tid >> 4;

    if (tid < 64) Ls[tid] = g_L[b0 + tid];
    __syncthreads();

    float acc[4][4][4];                   // [row][colgroup][col]
#pragma unroll
    for (int a = 0; a < 4; ++a)
#pragma unroll
        for (int g = 0; g < 4; ++g)
#pragma unroll
            for (int c = 0; c < 4; ++c) acc[a][g][c] = 0.f;

    const bool vecOK = ((Nn & 3) == 0);

    for (int n0 = nstart; n0 < nend; n0 += 32) {
        __syncthreads();   // protect smem reuse from previous tile's readers
        // load pattern tile 32x256 (zero-fill past nend)
#pragma unroll
        for (int i = 0; i < 8; ++i) {
            int q = tid + i * 256;            // 0..2047
            int r = q >> 6;                   // 0..31
            int c = (q & 63) * 4;
            int n = n0 + r;
            float4 v = (n < nend) ? *(const float4*)&pat[(long)n * D_DIM + c]
                                  : make_float4(0.f, 0.f, 0.f, 0.f);
            *(float4*)&Ps[r][c] = v;
        }
        // load z tile 64x32, compute weights, store transposed to Ws
#pragma unroll
        for (int i = 0; i < 2; ++i) {
            int q = tid + i * 256;            // 0..511
            int r = q >> 3;                   // b-row in tile, 0..63
            int j = (q & 7) * 4;              // n-col in tile
            int n = n0 + j;
            float lb = Ls[r];
            float w0 = 0.f, w1 = 0.f, w2 = 0.f, w3 = 0.f;
            if (vecOK && (n + 4 <= nend)) {
                float4 z4 = *(const float4*)&g_z[(long)(b0 + r) * Nn + n];
                w0 = expf(z4.x - lb); w1 = expf(z4.y - lb);
                w2 = expf(z4.z - lb); w3 = expf(z4.w - lb);
            } else {
                if (n + 0 < nend) w0 = expf(g_z[(long)(b0 + r) * Nn + n + 0] - lb);
                if (n + 1 < nend) w1 = expf(g_z[(long)(b0 + r) * Nn + n + 1] - lb);
                if (n + 2 < nend) w2 = expf(g_z[(long)(b0 + r) * Nn + n + 2] - lb);
                if (n + 3 < nend) w3 = expf(g_z[(long)(b0 + r) * Nn + n + 3] - lb);
            }
            Ws[j + 0][r] = w0; Ws[j + 1][r] = w1;
            Ws[j + 2][r] = w2; Ws[j + 3][r] = w3;
        }
        __syncthreads();
        // column max over the 64 rows of this tile -> atomicMax
        if (tid < 128) {
            int j = tid >> 2;
            int qr = (tid & 3) * 16;
            float mx = 0.f;
#pragma unroll
            for (int r = 0; r < 16; ++r) mx = fmaxf(mx, Ws[j][qr + r]);
            mx = fmaxf(mx, __shfl_xor_sync(0xffffffffu, mx, 1));
            mx = fmaxf(mx, __shfl_xor_sync(0xffffffffu, mx, 2));
            if ((tid & 3) == 0 && (n0 + j) < nend)
                atomicMax(&g_cmax[n0 + j], __float_as_int(mx));
        }
        // accumulate retrieved: acc[r][c] += w[r][j] * Ps[j][c]
#pragma unroll
        for (int j = 0; j < 32; ++j) {
            float wv[4];
            *(float4*)wv = *(const float4*)&Ws[j][ty * 4];
#pragma unroll
            for (int g = 0; g < 4; ++g) {
                float pv[4];
                *(float4*)pv = *(const float4*)&Ps[j][g * 64 + tx * 4];
#pragma unroll
                for (int mi = 0; mi < 4; ++mi)
#pragma unroll
                    for (int ci = 0; ci < 4; ++ci)
                        acc[mi][g][ci] = fmaf(wv[mi], pv[ci], acc[mi][g][ci]);
            }
        }
    }
    // write split partials (deterministic reduction later)
    const long base = ((long)split * B_DIM + b0) * D_DIM;
#pragma unroll
    for (int mi = 0; mi < 4; ++mi) {
        int r = ty * 4 + mi;
#pragma unroll
        for (int g = 0; g < 4; ++g) {
            float4 o = make_float4(acc[mi][g][0], acc[mi][g][1], acc[mi][g][2], acc[mi][g][3]);
            *(float4*)&g_part[base + (long)r * D_DIM + g * 64 + tx * 4] = o;
        }
    }
}

// ---------------- reduce split partials into retrieved -----------------------
__global__ void reduce_ret_kernel(float* __restrict__ out, int nsplit) {
    int i = blockIdx.x * 256 + threadIdx.x;      // float4 index, 0..65535
    float4 s = make_float4(0.f, 0.f, 0.f, 0.f);
    for (int sp = 0; sp < nsplit; ++sp) {
        float4 v = *(const float4*)&g_part[(long)sp * (B_DIM * D_DIM) + (long)i * 4];
        s.x += v.x; s.y += v.y; s.z += v.z; s.w += v.w;
    }
    *(float4*)&out[(long)i * 4] = s;
}

// ---------------- final depth reinforcement ----------------------------------
__global__ void depths_kernel(const float* __restrict__ depths,
                              float* __restrict__ out, int Nn) {
    int i = blockIdx.x * 256 + threadIdx.x;
    if (i >= Nn) return;
    float d = depths[i];
    float maxw = __int_as_float(g_cmax[i]);
    float logd = log1pf(d);
    float dommax = fmaxf(__int_as_float(g_logdmax), 1e-8f);
    float dom = logd / dommax;
    float rate = 0.01f * (1.0f - 0.7f * dom);
    float nd = d + ((maxw > 0.1f) ? rate * maxw : 0.0f);
    out[B_DIM * D_DIM + i] = nd;
}

// ---------------- launch ------------------------------------------------------
extern "C" void kernel_launch(void* const* d_in, const int* in_sizes, int n_in,
                              void* d_out, int out_size) {
    const float* state   = (const float*)d_in[0];
    const float* W       = (const float*)d_in[1];
    const float* pat     = (const float*)d_in[2];
    const float* depths  = (const float*)d_in[3];
    const float* gate    = (const float*)d_in[4];
    float* out = (float*)d_out;
    const int Nn = in_sizes[3];

    const int nbN = (Nn + 255) / 256;
    init_kernel<<<nbN, 256>>>(Nn);
    proj_kernel<<<B_DIM, 256>>>(state, W);
    bias_kernel<<<nbN, 256>>>(depths, gate, Nn);

    const int ntiles = (Nn + 127) / 128;
    gemm_z_kernel<<<dim3(B_DIM / 128, ntiles), 256>>>(pat, Nn);

    lse_kernel<<<B_DIM, 256>>>(Nn);

    const int nsplit = (Nn + 2047) / 2048;
    out_gemm_kernel<<<dim3(B_DIM / 64, nsplit), 256>>>(pat, Nn, nsplit);

    reduce_ret_kernel<<<(B_DIM * D_DIM / 4) / 256, 256>>>(out, nsplit);
    depths_kernel<<<nbN, 256>>>(depths, out, Nn);
}

// round 3
// speedup vs baseline: 1.5241x; 1.0045x over previous
#include <cuda_runtime.h>
#include <math.h>

// Problem shape (from reference): B=1024, D=256, N=100000 (runtime from in_sizes)
#define B_DIM 1024
#define D_DIM 256
#define MAXN  100352            // capacity (multiple of 128)
#define MAXSPLIT 64             // capacity for N-splits of 2048

// ---------------- scratch (device globals; no allocation in kernel_launch) ---
__device__ float g_proj[B_DIM * D_DIM];                    // 1 MB
__device__ float g_bias[MAXN];                             // 0.4 MB
__device__ float g_L[B_DIM];                               // logsumexp per row
__device__ float g_z[(size_t)B_DIM * MAXN];                // ~411 MB logits
__device__ float g_part[(size_t)MAXSPLIT * B_DIM * D_DIM]; // 67 MB split partials
__device__ int   g_cmax[MAXN];                             // col-max(w) as float bits (>=0)
__device__ int   g_logdmax;                                // max log1p(depth) as float bits

// ---------------- init: zero atomically-reduced scratch ----------------------
__global__ void init_kernel(int Nn) {
    int i = blockIdx.x * blockDim.x + threadIdx.x;
    if (i < Nn) g_cmax[i] = 0;
    if (i == 0) g_logdmax = 0;
}

// ---------------- projection: proj[b][j] = sum_d state[b][d] * W[j][d] -------
__global__ void proj_kernel(const float* __restrict__ state,
                            const float* __restrict__ W) {
    __shared__ float s[D_DIM];
    int b = blockIdx.x, j = threadIdx.x;
    s[j] = state[b * D_DIM + j];
    __syncthreads();
    const float* wr = W + j * D_DIM;
    float acc = 0.f;
#pragma unroll 16
    for (int d = 0; d < D_DIM; ++d) acc = fmaf(s[d], wr[d], acc);
    g_proj[b * D_DIM + j] = acc;
}

// ---------------- bias = log(clip(depth)) + log(clip(gate)); max log1p(depth)
__global__ void bias_kernel(const float* __restrict__ depths,
                            const float* __restrict__ gate, int Nn) {
    int i = blockIdx.x * 256 + threadIdx.x;
    float lv = 0.f;
    if (i < Nn) {
        float d = depths[i], g = gate[i];
        g_bias[i] = logf(fmaxf(d, 1e-8f)) + logf(fmaxf(g, 1e-8f));
        lv = log1pf(d);
    }
    __shared__ float red[256];
    red[threadIdx.x] = lv;
    __syncthreads();
#pragma unroll
    for (int o = 128; o > 0; o >>= 1) {
        if (threadIdx.x < o) red[threadIdx.x] = fmaxf(red[threadIdx.x], red[threadIdx.x + o]);
        __syncthreads();
    }
    if (threadIdx.x == 0) atomicMax(&g_logdmax, __float_as_int(red[0]));
}

// ---------------- SGEMM1: z[m][n] = proj[m][:] . pat[n][:] + bias[n] ---------
// Tile 128x128, K-step 8, 256 threads, 8x8 micro-tile, double-buffered smem.
__global__ __launch_bounds__(256) void gemm_z_kernel(const float* __restrict__ pat,
                                                     int Nn) {
    __shared__ float As[2][8][128];
    __shared__ float Bs[2][8][128];
    const int m0 = blockIdx.x * 128;         // 8 m-tiles
    const int n0 = blockIdx.y * 128;         // ceil(Nn/128) n-tiles
    const int tid = threadIdx.x;
    const int lrow = tid >> 1;               // 0..127
    const int lk   = (tid & 1) * 4;          // 0 or 4
    const int tx = tid & 15, ty = tid >> 4;

    const float* aptr = g_proj + (m0 + lrow) * D_DIM + lk;
    const long  brow  = (long)n0 + lrow;
    const float* bptr = pat + brow * D_DIM + lk;
    const bool  bval  = brow < Nn;

    float acc0[4][4], acc1[4][4], acc2[4][4], acc3[4][4];
#pragma unroll
    for (int i = 0; i < 4; ++i)
#pragma unroll
        for (int j = 0; j < 4; ++j) { acc0[i][j] = acc1[i][j] = acc2[i][j] = acc3[i][j] = 0.f; }

    float4 ar = *(const float4*)aptr;
    float4 br = bval ? *(const float4*)bptr : make_float4(0.f, 0.f, 0.f, 0.f);
    int buf = 0;
    As[0][lk + 0][lrow] = ar.x; As[0][lk + 1][lrow] = ar.y;
    As[0][lk + 2][lrow] = ar.z; As[0][lk + 3][lrow] = ar.w;
    Bs[0][lk + 0][lrow] = br.x; Bs[0][lk + 1][lrow] = br.y;
    Bs[0][lk + 2][lrow] = br.z; Bs[0][lk + 3][lrow] = br.w;
    __syncthreads();

    for (int k0 = 0; k0 < D_DIM; k0 += 8) {
        const bool more = (k0 + 8) < D_DIM;
        if (more) {
            ar = *(const float4*)(aptr + k0 + 8);
            br = bval ? *(const float4*)(bptr + k0 + 8) : make_float4(0.f, 0.f, 0.f, 0.f);
        }
#pragma unroll
        for (int k = 0; k < 8; ++k) {
            float af0[4], af1[4], bf0[4], bf1[4];
            *(float4*)af0 = *(const float4*)&As[buf][k][ty * 4];
            *(float4*)af1 = *(const float4*)&As[buf][k][64 + ty * 4];
            *(float4*)bf0 = *(const float4*)&Bs[buf][k][tx * 4];
            *(float4*)bf1 = *(const float4*)&Bs[buf][k][64 + tx * 4];
#pragma unroll
            for (int mi = 0; mi < 4; ++mi)
#pragma unroll
                for (int ni = 0; ni < 4; ++ni) {
                    acc0[mi][ni] = fmaf(af0[mi], bf0[ni], acc0[mi][ni]);
                    acc1[mi][ni] = fmaf(af0[mi], bf1[ni], acc1[mi][ni]);
                    acc2[mi][ni] = fmaf(af1[mi], bf0[ni], acc2[mi][ni]);
                    acc3[mi][ni] = fmaf(af1[mi], bf1[ni], acc3[mi][ni]);
                }
        }
        if (more) {
            As[buf ^ 1][lk + 0][lrow] = ar.x; As[buf ^ 1][lk + 1][lrow] = ar.y;
            As[buf ^ 1][lk + 2][lrow] = ar.z; As[buf ^ 1][lk + 3][lrow] = ar.w;
            Bs[buf ^ 1][lk + 0][lrow] = br.x; Bs[buf ^ 1][lk + 1][lrow] = br.y;
            Bs[buf ^ 1][lk + 2][lrow] = br.z; Bs[buf ^ 1][lk + 3][lrow] = br.w;
        }
        __syncthreads();
        buf ^= 1;
    }

    // epilogue: add bias, store z
    const bool vecOK = ((Nn & 3) == 0);
#pragma unroll
    for (int gm = 0; gm < 2; ++gm) {
#pragma unroll
        for (int mi = 0; mi < 4; ++mi) {
            const int m = m0 + gm * 64 + ty * 4 + mi;
#pragma unroll
            for (int gn = 0; gn < 2; ++gn) {
                const int c = gn * 64 + tx * 4;
                const long n = (long)n0 + c;
                float v[4];
#pragma unroll
                for (int ni = 0; ni < 4; ++ni)
                    v[ni] = (gm == 0) ? ((gn == 0) ? acc0[mi][ni] : acc1[mi][ni])
                                      : ((gn == 0) ? acc2[mi][ni] : acc3[mi][ni]);
                if (vecOK && (n + 4 <= Nn)) {
                    float4 b4 = *(const float4*)&g_bias[n];
                    float4 o  = make_float4(v[0] + b4.x, v[1] + b4.y, v[2] + b4.z, v[3] + b4.w);
                    *(float4*)&g_z[(long)m * Nn + n] = o;
                } else {
#pragma unroll
                    for (int ni = 0; ni < 4; ++ni)
                        if (n + ni < Nn) g_z[(long)m * Nn + n + ni] = v[ni] + g_bias[n + ni];
                }
            }
        }
    }
}

// ---------------- row logsumexp: L[b] = m + log(sum exp(z-m)) ----------------
__global__ void lse_kernel(int Nn) {
    const int b = blockIdx.x, tid = threadIdx.x;
    const float* zr = g_z + (long)b * Nn;
    float m = -INFINITY, s = 0.f;
    const int n4 = Nn >> 2;
    const float4* zr4 = (const float4*)zr;
    for (int i = tid; i < n4; i += 256) {
        float4 v = zr4[i];
        float mv = fmaxf(fmaxf(v.x, v.y), fmaxf(v.z, v.w));
        if (mv > m) { s *= expf(m - mv); m = mv; }
        s += expf(v.x - m) + expf(v.y - m) + expf(v.z - m) + expf(v.w - m);
    }
    for (int i = (n4 << 2) + tid; i < Nn; i += 256) {   // tail (Nn%4)
        float v = zr[i];
        if (v > m) { s *= expf(m - v); m = v; }
        s += expf(v - m);
    }
    __shared__ float sm[256], ss[256];
    sm[tid] = m; ss[tid] = s;
    __syncthreads();
#pragma unroll
    for (int o = 128; o > 0; o >>= 1) {
        if (tid < o) {
            float m2 = sm[tid + o], s2 = ss[tid + o];
            float M = fmaxf(sm[tid], m2);
            ss[tid] = ss[tid] * expf(sm[tid] - M) + s2 * expf(m2 - M);
            sm[tid] = M;
        }
        __syncthreads();
    }
    if (tid == 0) g_L[b] = sm[0] + logf(ss[0]);
}

// ---------------- SGEMM2: retrieved partials + column max of weights ---------
// CTA: 64 b-rows x one 2048-wide N chunk. Inner tile: 32 patterns.
__global__ __launch_bounds__(256) void out_gemm_kernel(const float* __restrict__ pat,
                                                       int Nn, int nsplit) {
    __shared__ float Ps[32][256];       // pattern tile [n][d]
    __shared__ float Ws[32][68];        // weights [n][b-in-tile], padded
    __shared__ float Ls[64];
    const int b0 = blockIdx.x * 64;       // 16 row tiles
    const int split = blockIdx.y;
    const int nstart = split * 2048;
    const int nend = min(nstart + 2048, Nn);
    const int tid = threadIdx.x;
    const int tx = tid & 15, ty = tid >> 4;

    if (tid < 64) Ls[tid] = g_L[b0 + tid];
    __syncthreads();

    float acc[4][4][4];                   // [row][colgroup][col]
#pragma unroll
    for (int a = 0; a < 4; ++a)
#pragma unroll
        for (int g = 0; g < 4; ++g)
#pragma unroll
            for (int c = 0; c < 4; ++c) acc[a][g][c] = 0.f;

    const bool vecOK = ((Nn & 3) == 0);

    for (int n0 = nstart; n0 < nend; n0 += 32) {
        __syncthreads();   // protect smem reuse from previous tile's readers
        // load pattern tile 32x256 (zero-fill past nend)
#pragma unroll
        for (int i = 0; i < 8; ++i) {
            int q = tid + i * 256;            // 0..2047
            int r = q >> 6;                   // 0..31
            int c = (q & 63) * 4;
            int n = n0 + r;
            float4 v = (n < nend) ? *(const float4*)&pat[(long)n * D_DIM + c]
                                  : make_float4(0.f, 0.f, 0.f, 0.f);
            *(float4*)&Ps[r][c] = v;
        }
        // load z tile 64x32, compute weights, store transposed to Ws
#pragma unroll
        for (int i = 0; i < 2; ++i) {
            int q = tid + i * 256;            // 0..511
            int r = q >> 3;                   // b-row in tile, 0..63
            int j = (q & 7) * 4;              // n-col in tile
            int n = n0 + j;
            float lb = Ls[r];
            float w0 = 0.f, w1 = 0.f, w2 = 0.f, w3 = 0.f;
            if (vecOK && (n + 4 <= nend)) {
                float4 z4 = *(const float4*)&g_z[(long)(b0 + r) * Nn + n];
                w0 = expf(z4.x - lb); w1 = expf(z4.y - lb);
                w2 = expf(z4.z - lb); w3 = expf(z4.w - lb);
            } else {
                if (n + 0 < nend) w0 = expf(g_z[(long)(b0 + r) * Nn + n + 0] - lb);
                if (n + 1 < nend) w1 = expf(g_z[(long)(b0 + r) * Nn + n + 1] - lb);
                if (n + 2 < nend) w2 = expf(g_z[(long)(b0 + r) * Nn + n + 2] - lb);
                if (n + 3 < nend) w3 = expf(g_z[(long)(b0 + r) * Nn + n + 3] - lb);
            }
            Ws[j + 0][r] = w0; Ws[j + 1][r] = w1;
            Ws[j + 2][r] = w2; Ws[j + 3][r] = w3;
        }
        __syncthreads();
        // column max over the 64 rows of this tile -> atomicMax
        if (tid < 128) {
            int j = tid >> 2;
            int qr = (tid & 3) * 16;
            float mx = 0.f;
#pragma unroll
            for (int r = 0; r < 16; ++r) mx = fmaxf(mx, Ws[j][qr + r]);
            mx = fmaxf(mx, __shfl_xor_sync(0xffffffffu, mx, 1));
            mx = fmaxf(mx, __shfl_xor_sync(0xffffffffu, mx, 2));
            if ((tid & 3) == 0 && (n0 + j) < nend)
                atomicMax(&g_cmax[n0 + j], __float_as_int(mx));
        }
        // accumulate retrieved: acc[r][c] += w[r][j] * Ps[j][c]
#pragma unroll
        for (int j = 0; j < 32; ++j) {
            float wv[4];
            *(float4*)wv = *(const float4*)&Ws[j][ty * 4];
#pragma unroll
            for (int g = 0; g < 4; ++g) {
                float pv[4];
                *(float4*)pv = *(const float4*)&Ps[j][g * 64 + tx * 4];
#pragma unroll
                for (int mi = 0; mi < 4; ++mi)
#pragma unroll
                    for (int ci = 0; ci < 4; ++ci)
                        acc[mi][g][ci] = fmaf(wv[mi], pv[ci], acc[mi][g][ci]);
            }
        }
    }
    // write split partials (deterministic reduction later)
    const long base = ((long)split * B_DIM + b0) * D_DIM;
#pragma unroll
    for (int mi = 0; mi < 4; ++mi) {
        int r = ty * 4 + mi;
#pragma unroll
        for (int g = 0; g < 4; ++g) {
            float4 o = make_float4(acc[mi][g][0], acc[mi][g][1], acc[mi][g][2], acc[mi][g][3]);
            *(float4*)&g_part[base + (long)r * D_DIM + g * 64 + tx * 4] = o;
        }
    }
}

// ---------------- reduce split partials into retrieved -----------------------
__global__ void reduce_ret_kernel(float* __restrict__ out, int nsplit) {
    int i = blockIdx.x * 256 + threadIdx.x;      // float4 index, 0..65535
    float4 s = make_float4(0.f, 0.f, 0.f, 0.f);
    for (int sp = 0; sp < nsplit; ++sp) {
        float4 v = *(const float4*)&g_part[(long)sp * (B_DIM * D_DIM) + (long)i * 4];
        s.x += v.x; s.y += v.y; s.z += v.z; s.w += v.w;
    }
    *(float4*)&out[(long)i * 4] = s;
}

// ---------------- final depth reinforcement ----------------------------------
__global__ void depths_kernel(const float* __restrict__ depths,
                              float* __restrict__ out, int Nn) {
    int i = blockIdx.x * 256 + threadIdx.x;
    if (i >= Nn) return;
    float d = depths[i];
    float maxw = __int_as_float(g_cmax[i]);
    float logd = log1pf(d);
    float dommax = fmaxf(__int_as_float(g_logdmax), 1e-8f);
    float dom = logd / dommax;
    float rate = 0.01f * (1.0f - 0.7f * dom);
    float nd = d + ((maxw > 0.1f) ? rate * maxw : 0.0f);
    out[B_DIM * D_DIM + i] = nd;
}

// ---------------- launch ------------------------------------------------------
extern "C" void kernel_launch(void* const* d_in, const int* in_sizes, int n_in,
                              void* d_out, int out_size) {
    const float* state   = (const float*)d_in[0];
    const float* W       = (const float*)d_in[1];
    const float* pat     = (const float*)d_in[2];
    const float* depths  = (const float*)d_in[3];
    const float* gate    = (const float*)d_in[4];
    float* out = (float*)d_out;
    const int Nn = in_sizes[3];

    const int nbN = (Nn + 255) / 256;
    init_kernel<<<nbN, 256>>>(Nn);
    proj_kernel<<<B_DIM, 256>>>(state, W);
    bias_kernel<<<nbN, 256>>>(depths, gate, Nn);

    const int ntiles = (Nn + 127) / 128;
    gemm_z_kernel<<<dim3(B_DIM / 128, ntiles), 256>>>(pat, Nn);

    lse_kernel<<<B_DIM, 256>>>(Nn);

    const int nsplit = (Nn + 2047) / 2048;
    out_gemm_kernel<<<dim3(B_DIM / 64, nsplit), 256>>>(pat, Nn, nsplit);

    reduce_ret_kernel<<<(B_DIM * D_DIM / 4) / 256, 256>>>(out, nsplit);
    depths_kernel<<<nbN, 256>>>(depths, out, Nn);
}

// round 5
// speedup vs baseline: 2.3825x; 1.5632x over previous
#include <cuda_runtime.h>
#include <cuda_bf16.h>
#include <mma.h>
#include <math.h>
#include <stdint.h>

using namespace nvcuda;

#define B_DIM 1024
#define D_DIM 256
#define NPAD  100352
#define NSPLIT 32

__device__ __nv_bfloat16 g_projhi[B_DIM * D_DIM];
__device__ __nv_bfloat16 g_projlo[B_DIM * D_DIM];
__device__ float g_bias[NPAD];
__device__ float g_z[(size_t)B_DIM * NPAD];
__device__ float g_L[B_DIM];
__device__ __nv_bfloat16 g_pathi[(size_t)NPAD * D_DIM];
__device__ __nv_bfloat16 g_patlo[(size_t)NPAD * D_DIM];
__device__ float g_part[(size_t)NSPLIT * B_DIM * D_DIM];
__device__ unsigned g_cmax[NPAD];   // bits of max weight (>=0) per column
__device__ int g_logdmax;

// ---- fast exp on FMA pipe (rel err ~3e-6), args <= 0 expected ---------------
__device__ __forceinline__ float fexp(float x) {
    float y = fmaxf(x * 1.44269504088896f, -126.0f);
    float k = rintf(y);
    float f = y - k;
    float p = 1.3333558146e-3f;
    p = fmaf(p, f, 9.6181291076e-3f);
    p = fmaf(p, f, 5.5504108664e-2f);
    p = fmaf(p, f, 2.4022650696e-1f);
    p = fmaf(p, f, 6.9314718056e-1f);
    p = fmaf(p, f, 1.0f);
    return p * __int_as_float(((int)k + 127) << 23);
}
__device__ __forceinline__ uint32_t pk2bf(float lo, float hi) {
    uint32_t d; asm("cvt.rn.bf16x2.f32 %0, %1, %2;" : "=r"(d) : "f"(hi), "f"(lo)); return d;
}
__device__ __forceinline__ float wlo(uint32_t p) { return __uint_as_float(p << 16); }
__device__ __forceinline__ float whi(uint32_t p) { return __uint_as_float(p & 0xFFFF0000u); }

// -------------------- prep ----------------------------------------------------
__global__ void init_kernel(int Nn) {
    int i = blockIdx.x * blockDim.x + threadIdx.x;
    if (i < Nn) g_cmax[i] = 0u;
    if (i == 0) g_logdmax = 0;
}

__global__ void proj_kernel(const float* __restrict__ state, const float* __restrict__ W) {
    __shared__ float s[D_DIM];
    int b = blockIdx.x, j = threadIdx.x;
    s[j] = state[b * D_DIM + j];
    __syncthreads();
    const float* wr = W + j * D_DIM;
    float acc = 0.f;
#pragma unroll 16
    for (int d = 0; d < D_DIM; ++d) acc = fmaf(s[d], wr[d], acc);
    __nv_bfloat16 h = __float2bfloat16(acc);
    g_projhi[b * D_DIM + j] = h;
    g_projlo[b * D_DIM + j] = __float2bfloat16(acc - __bfloat162float(h));
}

__global__ void bias_kernel(const float* __restrict__ depths,
                            const float* __restrict__ gate, int Nn) {
    int i = blockIdx.x * 256 + threadIdx.x;
    float lv = 0.f;
    if (i < Nn) {
        float d = depths[i], g = gate[i];
        g_bias[i] = logf(fmaxf(d, 1e-8f)) + logf(fmaxf(g, 1e-8f));
        lv = log1pf(d);
    }
    __shared__ float red[256];
    red[threadIdx.x] = lv;
    __syncthreads();
#pragma unroll
    for (int o = 128; o > 0; o >>= 1) {
        if (threadIdx.x < o) red[threadIdx.x] = fmaxf(red[threadIdx.x], red[threadIdx.x + o]);
        __syncthreads();
    }
    if (threadIdx.x == 0) atomicMax(&g_logdmax, __float_as_int(red[0]));
}

// patterns -> bf16 hi/lo, zero-padded to NPAD rows
__global__ void patprep_kernel(const float* __restrict__ pat, int Nn) {
    long i = (long)blockIdx.x * 256 + threadIdx.x;   // one float4 per thread
    long e0 = i * 4;
    long n = e0 >> 8;
    float4 v = (n < Nn) ? *(const float4*)&pat[e0] : make_float4(0.f, 0.f, 0.f, 0.f);
    uint32_t h0 = pk2bf(v.x, v.y), h1 = pk2bf(v.z, v.w);
    uint32_t l0 = pk2bf(v.x - wlo(h0), v.y - whi(h0));
    uint32_t l1 = pk2bf(v.z - wlo(h1), v.w - whi(h1));
    *(uint2*)&g_pathi[e0] = make_uint2(h0, h1);
    *(uint2*)&g_patlo[e0] = make_uint2(l0, l1);
}

// -------------------- gemm1: z = proj @ pat^T + bias (wmma bf16 3-pass) -------
#define SM1_BYTES 67584
__global__ __launch_bounds__(256) void gemm1_kernel(int Nn) {
    extern __shared__ char sm[];
    __nv_bfloat16* Ah = (__nv_bfloat16*)sm;              // [128][40]
    __nv_bfloat16* Al = Ah + 128 * 40;
    __nv_bfloat16* Bh = Al + 128 * 40;
    __nv_bfloat16* Bl = Bh + 128 * 40;
    float* Cs = (float*)sm;                               // [128][132] overlay
    const int tid = threadIdx.x, wid = tid >> 5;
    const int wm = wid >> 2, wn = wid & 3;               // 2 x 4 warp grid
    const int m0 = blockIdx.x * 128;
    const long n0 = (long)blockIdx.y * 128;

    wmma::fragment<wmma::accumulator, 16, 16, 16, float> acc[4][2];
#pragma unroll
    for (int mi = 0; mi < 4; ++mi)
#pragma unroll
        for (int ni = 0; ni < 2; ++ni) wmma::fill_fragment(acc[mi][ni], 0.0f);

    const int row = tid >> 1, cg = (tid & 1) * 16;
    for (int kc = 0; kc < 8; ++kc) {
        const int k0 = kc * 32;
        const uint4* pa = (const uint4*)&g_projhi[(m0 + row) * D_DIM + k0 + cg];
        const uint4* pal = (const uint4*)&g_projlo[(m0 + row) * D_DIM + k0 + cg];
        const uint4* pb = (const uint4*)&g_pathi[(n0 + row) * D_DIM + k0 + cg];
        const uint4* pbl = (const uint4*)&g_patlo[(n0 + row) * D_DIM + k0 + cg];
        *(uint4*)&Ah[row * 40 + cg] = pa[0];  *(uint4*)&Ah[row * 40 + cg + 8] = pa[1];
        *(uint4*)&Al[row * 40 + cg] = pal[0]; *(uint4*)&Al[row * 40 + cg + 8] = pal[1];
        *(uint4*)&Bh[row * 40 + cg] = pb[0];  *(uint4*)&Bh[row * 40 + cg + 8] = pb[1];
        *(uint4*)&Bl[row * 40 + cg] = pbl[0]; *(uint4*)&Bl[row * 40 + cg + 8] = pbl[1];
        __syncthreads();
#pragma unroll
        for (int kk = 0; kk < 32; kk += 16) {
            wmma::fragment<wmma::matrix_a, 16, 16, 16, __nv_bfloat16, wmma::row_major> ah[4], al[4];
            wmma::fragment<wmma::matrix_b, 16, 16, 16, __nv_bfloat16, wmma::col_major> bh[2], bl[2];
#pragma unroll
            for (int mi = 0; mi < 4; ++mi) {
                wmma::load_matrix_sync(ah[mi], &Ah[(wm * 64 + mi * 16) * 40 + kk], 40);
                wmma::load_matrix_sync(al[mi], &Al[(wm * 64 + mi * 16) * 40 + kk], 40);
            }
#pragma unroll
            for (int ni = 0; ni < 2; ++ni) {
                wmma::load_matrix_sync(bh[ni], &Bh[(wn * 32 + ni * 16) * 40 + kk], 40);
                wmma::load_matrix_sync(bl[ni], &Bl[(wn * 32 + ni * 16) * 40 + kk], 40);
            }
#pragma unroll
            for (int mi = 0; mi < 4; ++mi)
#pragma unroll
                for (int ni = 0; ni < 2; ++ni) {
                    wmma::mma_sync(acc[mi][ni], ah[mi], bh[ni], acc[mi][ni]);
                    wmma::mma_sync(acc[mi][ni], al[mi], bh[ni], acc[mi][ni]);
                    wmma::mma_sync(acc[mi][ni], ah[mi], bl[ni], acc[mi][ni]);
                }
        }
        __syncthreads();
    }
#pragma unroll
    for (int mi = 0; mi < 4; ++mi)
#pragma unroll
        for (int ni = 0; ni < 2; ++ni)
            wmma::store_matrix_sync(&Cs[(wm * 64 + mi * 16) * 132 + wn * 32 + ni * 16],
                                    acc[mi][ni], 132, wmma::mem_row_major);
    __syncthreads();
    const int r2 = tid >> 1, hc = (tid & 1) * 64;
    const int m = m0 + r2;
    float* zrow = g_z + (long)m * NPAD;
#pragma unroll
    for (int j = 0; j < 64; j += 4) {
        long n = n0 + hc + j;
        if (n + 4 <= Nn) {
            float4 b4 = *(const float4*)&g_bias[n];
            float4 c4 = *(const float4*)&Cs[r2 * 132 + hc + j];
            *(float4*)&zrow[n] = make_float4(c4.x + b4.x, c4.y + b4.y, c4.z + b4.z, c4.w + b4.w);
        } else {
            for (int q = 0; q < 4; ++q)
                if (n + q < Nn) zrow[n + q] = Cs[r2 * 132 + hc + j + q] + g_bias[n + q];
        }
    }
}

// -------------------- row logsumexp --------------------------------------------
__global__ void lse_kernel(int Nn) {
    const int b = blockIdx.x, tid = threadIdx.x;
    const float* zr = g_z + (long)b * NPAD;
    float m = -3.0e38f, s = 0.f;
    for (long i = tid * 4; i + 4 <= Nn; i += 1024) {
        float4 v = *(const float4*)&zr[i];
        float mv = fmaxf(fmaxf(v.x, v.y), fmaxf(v.z, v.w));
        if (mv > m) { s *= fexp(m - mv); m = mv; }
        s += fexp(v.x - m) + fexp(v.y - m) + fexp(v.z - m) + fexp(v.w - m);
    }
    for (long i = (long)(Nn & ~3) + tid; i < Nn; i += 256) {
        float v = zr[i];
        if (v > m) { s *= fexp(m - v); m = v; }
        s += fexp(v - m);
    }
    __shared__ float sm[256], ss[256];
    sm[tid] = m; ss[tid] = s;
    __syncthreads();
#pragma unroll
    for (int o = 128; o > 0; o >>= 1) {
        if (tid < o) {
            float m2 = sm[tid + o], s2 = ss[tid + o];
            float M = fmaxf(sm[tid], m2);
            ss[tid] = ss[tid] * fexp(sm[tid] - M) + s2 * fexp(m2 - M);
            sm[tid] = M;
        }
        __syncthreads();
    }
    if (tid == 0) g_L[b] = sm[0] + logf(ss[0]);
}

// -------------------- gemm2: part = exp(z-L) @ pat + colmax --------------------
#define SM2_BYTES 135168
__global__ __launch_bounds__(512) void gemm2_kernel(int Nn, int CHv) {
    extern __shared__ char sm[];
    __nv_bfloat16* Ah = (__nv_bfloat16*)sm;              // [128][40] weights hi
    __nv_bfloat16* Al = Ah + 128 * 40;
    __nv_bfloat16* Bh = Al + 128 * 40;                   // [32][264] patterns hi
    __nv_bfloat16* Bl = Bh + 32 * 264;
    float* Cs = (float*)sm;                               // [128][264] overlay
    __shared__ unsigned scm[32];
    const int tid = threadIdx.x, wid = tid >> 5, lane = tid & 31;
    const int wm = wid & 1, wd = wid >> 1;               // 2 x 8 warp grid
    const int m0 = blockIdx.x * 128;
    const int sp = blockIdx.y;
    const int ns = sp * CHv, ne = min(ns + CHv, Nn);

    wmma::fragment<wmma::accumulator, 16, 16, 16, float> acc[4][2];
#pragma unroll
    for (int mi = 0; mi < 4; ++mi)
#pragma unroll
        for (int ni = 0; ni < 2; ++ni) wmma::fill_fragment(acc[mi][ni], 0.0f);

    const int r = tid >> 2, g = tid & 3, ng = g * 8;     // w tile assignment
    const float Lm = g_L[m0 + r];
    const float* zrow = g_z + (long)(m0 + r) * NPAD;
    const int rb = tid >> 4, cb = (tid & 15) * 16;       // B tile assignment
    if (tid < 32) scm[tid] = 0u;
    __syncthreads();

    for (int k0 = ns; k0 < ne; k0 += 32) {
        // weights tile 128x32: exp + pack + colmax
        float e[8];
        if (k0 + ng + 8 <= Nn) {
            float4 a = *(const float4*)&zrow[k0 + ng];
            float4 b = *(const float4*)&zrow[k0 + ng + 4];
            e[0] = fexp(a.x - Lm); e[1] = fexp(a.y - Lm);
            e[2] = fexp(a.z - Lm); e[3] = fexp(a.w - Lm);
            e[4] = fexp(b.x - Lm); e[5] = fexp(b.y - Lm);
            e[6] = fexp(b.z - Lm); e[7] = fexp(b.w - Lm);
        } else {
#pragma unroll
            for (int j = 0; j < 8; ++j) {
                long nn = k0 + ng + j;
                e[j] = (nn < Nn) ? fexp(zrow[nn] - Lm) : 0.f;
            }
        }
        uint32_t h0 = pk2bf(e[0], e[1]), h1 = pk2bf(e[2], e[3]);
        uint32_t h2 = pk2bf(e[4], e[5]), h3 = pk2bf(e[6], e[7]);
        *(uint4*)&Ah[r * 40 + ng] = make_uint4(h0, h1, h2, h3);
        *(uint4*)&Al[r * 40 + ng] = make_uint4(
            pk2bf(e[0] - wlo(h0), e[1] - whi(h0)), pk2bf(e[2] - wlo(h1), e[3] - whi(h1)),
            pk2bf(e[4] - wlo(h2), e[5] - whi(h2)), pk2bf(e[6] - wlo(h3), e[7] - whi(h3)));
        // column max: reduce over the 8 rows owned by this warp, then shared atomics
        uint32_t cm[8];
#pragma unroll
        for (int j = 0; j < 8; ++j) cm[j] = __float_as_uint(e[j]);
#pragma unroll
        for (int off = 4; off <= 16; off <<= 1)
#pragma unroll
            for (int j = 0; j < 8; ++j) {
                uint32_t o = __shfl_xor_sync(0xffffffffu, cm[j], off);
                cm[j] = (o > cm[j]) ? o : cm[j];
            }
        if ((lane >> 2) == 0) {
#pragma unroll
            for (int j = 0; j < 8; ++j) atomicMax(&scm[(lane & 3) * 8 + j], cm[j]);
        }
        // pattern tile 32x256 hi/lo
        {
            const uint4* pb = (const uint4*)&g_pathi[(long)(k0 + rb) * D_DIM + cb];
            const uint4* pbl = (const uint4*)&g_patlo[(long)(k0 + rb) * D_DIM + cb];
            *(uint4*)&Bh[rb * 264 + cb] = pb[0];  *(uint4*)&Bh[rb * 264 + cb + 8] = pb[1];
            *(uint4*)&Bl[rb * 264 + cb] = pbl[0]; *(uint4*)&Bl[rb * 264 + cb + 8] = pbl[1];
        }
        __syncthreads();
        if (tid < 32) {
            int n = k0 + tid;
            if (n < Nn && scm[tid]) atomicMax(&g_cmax[n], scm[tid]);
            scm[tid] = 0u;
        }
#pragma unroll
        for (int kk = 0; kk < 32; kk += 16) {
            wmma::fragment<wmma::matrix_a, 16, 16, 16, __nv_bfloat16, wmma::row_major> ah[4], al[4];
            wmma::fragment<wmma::matrix_b, 16, 16, 16, __nv_bfloat16, wmma::row_major> bh[2], bl[2];
#pragma unroll
            for (int mi = 0; mi < 4; ++mi) {
                wmma::load_matrix_sync(ah[mi], &Ah[(wm * 64 + mi * 16) * 40 + kk], 40);
                wmma::load_matrix_sync(al[mi], &Al[(wm * 64 + mi * 16) * 40 + kk], 40);
            }
#pragma unroll
            for (int ni = 0; ni < 2; ++ni) {
                wmma::load_matrix_sync(bh[ni], &Bh[kk * 264 + wd * 32 + ni * 16], 264);
                wmma::load_matrix_sync(bl[ni], &Bl[kk * 264 + wd * 32 + ni * 16], 264);
            }
#pragma unroll
            for (int mi = 0; mi < 4; ++mi)
#pragma unroll
                for (int ni = 0; ni < 2; ++ni) {
                    wmma::mma_sync(acc[mi][ni], ah[mi], bh[ni], acc[mi][ni]);
                    wmma::mma_sync(acc[mi][ni], al[mi], bh[ni], acc[mi][ni]);
                    wmma::mma_sync(acc[mi][ni], ah[mi], bl[ni], acc[mi][ni]);
                }
        }
        __syncthreads();
    }
#pragma unroll
    for (int mi = 0; mi < 4; ++mi)
#pragma unroll
        for (int ni = 0; ni < 2; ++ni)
            wmma::store_matrix_sync(&Cs[(wm * 64 + mi * 16) * 264 + wd * 32 + ni * 16],
                                    acc[mi][ni], 264, wmma::mem_row_major);
    __syncthreads();
    const int rr = tid >> 2, cgr = (tid & 3) * 64;
    const long ob = ((long)sp * B_DIM + m0 + rr) * D_DIM + cgr;
#pragma unroll
    for (int j = 0; j < 64; j += 4)
        *(float4*)&g_part[ob + j] = *(const float4*)&Cs[rr * 264 + cgr + j];
}

// -------------------- reductions / output --------------------------------------
__global__ void reduce_ret_kernel(float* __restrict__ out) {
    long i = blockIdx.x * 256 + threadIdx.x;
    float4 s = make_float4(0.f, 0.f, 0.f, 0.f);
    for (int sp = 0; sp < NSPLIT; ++sp) {
        float4 v = *(const float4*)&g_part[(long)sp * (B_DIM * D_DIM) + i * 4];
        s.x += v.x; s.y += v.y; s.z += v.z; s.w += v.w;
    }
    *(float4*)&out[i * 4] = s;
}

__global__ void depths_kernel(const float* __restrict__ depths,
                              float* __restrict__ out, int Nn) {
    int i = blockIdx.x * 256 + threadIdx.x;
    if (i >= Nn) return;
    float d = depths[i];
    float maxw = __uint_as_float(g_cmax[i]);
    float dom = log1pf(d) / fmaxf(__int_as_float(g_logdmax), 1e-8f);
    float rate = 0.01f * (1.0f - 0.7f * dom);
    out[B_DIM * D_DIM + i] = d + ((maxw > 0.1f) ? rate * maxw : 0.0f);
}

extern "C" void kernel_launch(void* const* d_in, const int* in_sizes, int n_in,
                              void* d_out, int out_size) {
    const float* state  = (const float*)d_in[0];
    const float* W      = (const float*)d_in[1];
    const float* pat    = (const float*)d_in[2];
    const float* depths = (const float*)d_in[3];
    const float* gate   = (const float*)d_in[4];
    float* out = (float*)d_out;
    const int Nn = in_sizes[3];

    cudaFuncSetAttribute(gemm1_kernel, cudaFuncAttributeMaxDynamicSharedMemorySize, SM1_BYTES);
    cudaFuncSetAttribute(gemm2_kernel, cudaFuncAttributeMaxDynamicSharedMemorySize, SM2_BYTES);

    const int nbN = (Nn + 255) / 256;
    init_kernel<<<nbN, 256>>>(Nn);
    proj_kernel<<<B_DIM, 256>>>(state, W);
    bias_kernel<<<nbN, 256>>>(depths, gate, Nn);
    patprep_kernel<<<(NPAD * D_DIM / 4) / 256, 256>>>(pat, Nn);

    const int ntiles = (Nn + 127) / 128;
    gemm1_kernel<<<dim3(B_DIM / 128, ntiles), 256, SM1_BYTES>>>(Nn);
    lse_kernel<<<B_DIM, 256>>>(Nn);

    const int CHv = ((Nn + NSPLIT * 32 - 1) / (NSPLIT * 32)) * 32;
    gemm2_kernel<<<dim3(B_DIM / 128, NSPLIT), 512, SM2_BYTES>>>(Nn, CHv);

    reduce_ret_kernel<<<(B_DIM * D_DIM / 4) / 256, 256>>>(out);
    depths_kernel<<<nbN, 256>>>(depths, out, Nn);
}

// round 6
// speedup vs baseline: 2.8578x; 1.1995x over previous
#include <cuda_runtime.h>
#include <cuda_bf16.h>
#include <mma.h>
#include <math.h>
#include <stdint.h>

using namespace nvcuda;

#define B_DIM 1024
#define D_DIM 256
#define NPAD  100352
#define NSPLIT 37
#define NTILE_MAX 800

__device__ __nv_bfloat16 g_projhi[B_DIM * D_DIM];
__device__ __nv_bfloat16 g_projlo[B_DIM * D_DIM];
__device__ float g_bias[NPAD];
__device__ float g_z[(size_t)B_DIM * NPAD];
__device__ float g_L[B_DIM];
__device__ float g_pm[(size_t)NTILE_MAX * B_DIM];
__device__ float g_ps[(size_t)NTILE_MAX * B_DIM];
__device__ __nv_bfloat16 g_pathi[(size_t)NPAD * D_DIM];
__device__ __nv_bfloat16 g_patlo[(size_t)NPAD * D_DIM];
__device__ float g_part[(size_t)NSPLIT * B_DIM * D_DIM];
__device__ unsigned g_cmax[NPAD];
__device__ int g_logdmax;

// fast exp on FMA pipe (rel err ~3e-6)
__device__ __forceinline__ float fexp(float x) {
    float y = fmaxf(x * 1.44269504088896f, -126.0f);
    float k = rintf(y);
    float f = y - k;
    float p = 1.3333558146e-3f;
    p = fmaf(p, f, 9.6181291076e-3f);
    p = fmaf(p, f, 5.5504108664e-2f);
    p = fmaf(p, f, 2.4022650696e-1f);
    p = fmaf(p, f, 6.9314718056e-1f);
    p = fmaf(p, f, 1.0f);
    return p * __int_as_float(((int)k + 127) << 23);
}
__device__ __forceinline__ uint32_t pk2bf(float lo, float hi) {
    uint32_t d; asm("cvt.rn.bf16x2.f32 %0, %1, %2;" : "=r"(d) : "f"(hi), "f"(lo)); return d;
}
__device__ __forceinline__ float wlo(uint32_t p) { return __uint_as_float(p << 16); }
__device__ __forceinline__ float whi(uint32_t p) { return __uint_as_float(p & 0xFFFF0000u); }
__device__ __forceinline__ uint32_t smem_u32(const void* p) {
    uint32_t a;
    asm("{ .reg .u64 t; cvta.to.shared.u64 t, %1; cvt.u32.u64 %0, t; }" : "=r"(a) : "l"(p));
    return a;
}
#define CP16(dst, src) \
    asm volatile("cp.async.cg.shared.global [%0], [%1], 16;" :: "r"(dst), "l"(src))
#define CP_COMMIT() asm volatile("cp.async.commit_group;" ::: "memory")
#define CP_WAIT0()  asm volatile("cp.async.wait_group 0;" ::: "memory")

// -------------------- prep ----------------------------------------------------
__global__ void init_kernel(int Nn) {
    int i = blockIdx.x * blockDim.x + threadIdx.x;
    if (i < Nn) g_cmax[i] = 0u;
    if (i == 0) g_logdmax = 0;
}

__global__ void proj_kernel(const float* __restrict__ state, const float* __restrict__ W) {
    __shared__ float s[D_DIM];
    int b = blockIdx.x, j = threadIdx.x;
    s[j] = state[b * D_DIM + j];
    __syncthreads();
    const float* wr = W + j * D_DIM;
    float acc = 0.f;
#pragma unroll 16
    for (int d = 0; d < D_DIM; ++d) acc = fmaf(s[d], wr[d], acc);
    __nv_bfloat16 h = __float2bfloat16(acc);
    g_projhi[b * D_DIM + j] = h;
    g_projlo[b * D_DIM + j] = __float2bfloat16(acc - __bfloat162float(h));
}

__global__ void bias_kernel(const float* __restrict__ depths,
                            const float* __restrict__ gate, int Nn) {
    int i = blockIdx.x * 256 + threadIdx.x;
    float lv = 0.f;
    if (i < Nn) {
        float d = depths[i], g = gate[i];
        g_bias[i] = logf(fmaxf(d, 1e-8f)) + logf(fmaxf(g, 1e-8f));
        lv = log1pf(d);
    }
    __shared__ float red[256];
    red[threadIdx.x] = lv;
    __syncthreads();
#pragma unroll
    for (int o = 128; o > 0; o >>= 1) {
        if (threadIdx.x < o) red[threadIdx.x] = fmaxf(red[threadIdx.x], red[threadIdx.x + o]);
        __syncthreads();
    }
    if (threadIdx.x == 0) atomicMax(&g_logdmax, __float_as_int(red[0]));
}

__global__ void patprep_kernel(const float* __restrict__ pat, int Nn) {
    long i = (long)blockIdx.x * 256 + threadIdx.x;
    long e0 = i * 4;
    long n = e0 >> 8;
    float4 v = (n < Nn) ? *(const float4*)&pat[e0] : make_float4(0.f, 0.f, 0.f, 0.f);
    uint32_t h0 = pk2bf(v.x, v.y), h1 = pk2bf(v.z, v.w);
    uint32_t l0 = pk2bf(v.x - wlo(h0), v.y - whi(h0));
    uint32_t l1 = pk2bf(v.z - wlo(h1), v.w - whi(h1));
    *(uint2*)&g_pathi[e0] = make_uint2(h0, h1);
    *(uint2*)&g_patlo[e0] = make_uint2(l0, l1);
}

// -------------------- gemm1 (double-buffered cp.async) -------------------------
// smem: 2 buffers x {Ah,Al,Bh,Bl}[128][40]; epilogue overlays float Cs[128][132]
#define SM1_BYTES 81920
__global__ __launch_bounds__(256) void gemm1_kernel(int Nn) {
    extern __shared__ char sm[];
    const uint32_t sb = smem_u32(sm);
    float* Cs = (float*)sm;
    const int tid = threadIdx.x, wid = tid >> 5;
    const int wm = wid >> 2, wn = wid & 3;
    const int m0 = blockIdx.x * 128;
    const long n0 = (long)blockIdx.y * 128;

    wmma::fragment<wmma::accumulator, 16, 16, 16, float> acc[4][2];
#pragma unroll
    for (int mi = 0; mi < 4; ++mi)
#pragma unroll
        for (int ni = 0; ni < 2; ++ni) wmma::fill_fragment(acc[mi][ni], 0.0f);

    const int row = tid >> 1, cg = (tid & 1) * 16;
    const char* sA  = (const char*)(g_projhi + (size_t)(m0 + row) * D_DIM + cg);
    const char* sAl = (const char*)(g_projlo + (size_t)(m0 + row) * D_DIM + cg);
    const char* sB  = (const char*)(g_pathi + (n0 + row) * D_DIM + cg);
    const char* sBl = (const char*)(g_patlo + (n0 + row) * D_DIM + cg);
    const uint32_t dbase = sb + row * 80 + cg * 2;

#define G1_ISSUE(c, buf) do { \
        uint32_t d = dbase + (buf) * 40960; long ob = (long)(c) * 64; \
        CP16(d +     0, sA  + ob); CP16(d +     16, sA  + ob + 16); \
        CP16(d + 10240, sAl + ob); CP16(d + 10256, sAl + ob + 16); \
        CP16(d + 20480, sB  + ob); CP16(d + 20496, sB  + ob + 16); \
        CP16(d + 30720, sBl + ob); CP16(d + 30736, sBl + ob + 16); \
        CP_COMMIT(); } while (0)

    G1_ISSUE(0, 0);
    CP_WAIT0();
    __syncthreads();

    for (int c = 0; c < 8; ++c) {
        const int cur = c & 1;
        if (c < 7) G1_ISSUE(c + 1, cur ^ 1);
        const __nv_bfloat16* Ah = (const __nv_bfloat16*)(sm + cur * 40960);
        const __nv_bfloat16* Al = (const __nv_bfloat16*)(sm + cur * 40960 + 10240);
        const __nv_bfloat16* Bh = (const __nv_bfloat16*)(sm + cur * 40960 + 20480);
        const __nv_bfloat16* Bl = (const __nv_bfloat16*)(sm + cur * 40960 + 30720);
#pragma unroll
        for (int kk = 0; kk < 32; kk += 16) {
            wmma::fragment<wmma::matrix_a, 16, 16, 16, __nv_bfloat16, wmma::row_major> ah[4], al[4];
            wmma::fragment<wmma::matrix_b, 16, 16, 16, __nv_bfloat16, wmma::col_major> bh[2], bl[2];
#pragma unroll
            for (int mi = 0; mi < 4; ++mi) {
                wmma::load_matrix_sync(ah[mi], &Ah[(wm * 64 + mi * 16) * 40 + kk], 40);
                wmma::load_matrix_sync(al[mi], &Al[(wm * 64 + mi * 16) * 40 + kk], 40);
            }
#pragma unroll
            for (int ni = 0; ni < 2; ++ni) {
                wmma::load_matrix_sync(bh[ni], &Bh[(wn * 32 + ni * 16) * 40 + kk], 40);
                wmma::load_matrix_sync(bl[ni], &Bl[(wn * 32 + ni * 16) * 40 + kk], 40);
            }
#pragma unroll
            for (int mi = 0; mi < 4; ++mi)
#pragma unroll
                for (int ni = 0; ni < 2; ++ni) {
                    wmma::mma_sync(acc[mi][ni], ah[mi], bh[ni], acc[mi][ni]);
                    wmma::mma_sync(acc[mi][ni], al[mi], bh[ni], acc[mi][ni]);
                    wmma::mma_sync(acc[mi][ni], ah[mi], bl[ni], acc[mi][ni]);
                }
        }
        if (c < 7) CP_WAIT0();
        __syncthreads();
    }

#pragma unroll
    for (int mi = 0; mi < 4; ++mi)
#pragma unroll
        for (int ni = 0; ni < 2; ++ni)
            wmma::store_matrix_sync(&Cs[(wm * 64 + mi * 16) * 132 + wn * 32 + ni * 16],
                                    acc[mi][ni], 132, wmma::mem_row_major);
    __syncthreads();

    // epilogue: add bias, write z, per-tile row max + sum(exp)
    const int r2 = tid >> 1, hc = (tid & 1) * 64;
    const int m = m0 + r2;
    float* zrow = g_z + (size_t)m * NPAD;
    const float* crow = Cs + r2 * 132 + hc;
    float vmax = -3.0e38f;
#pragma unroll
    for (int j = 0; j < 64; j += 4) {
        long n = n0 + hc + j;
        if (n + 4 <= Nn) {
            float4 b4 = *(const float4*)&g_bias[n];
            float4 c4 = *(const float4*)&crow[j];
            float4 o = make_float4(c4.x + b4.x, c4.y + b4.y, c4.z + b4.z, c4.w + b4.w);
            vmax = fmaxf(vmax, fmaxf(fmaxf(o.x, o.y), fmaxf(o.z, o.w)));
            *(float4*)&zrow[n] = o;
        } else {
            for (int q = 0; q < 4; ++q)
                if (n + q < Nn) {
                    float v = crow[j + q] + g_bias[n + q];
                    vmax = fmaxf(vmax, v);
                    zrow[n + q] = v;
                }
        }
    }
    float pmv = fmaxf(vmax, __shfl_xor_sync(0xffffffffu, vmax, 1));
    float s = 0.f;
#pragma unroll
    for (int j = 0; j < 64; j += 4) {
        long n = n0 + hc + j;
        if (n + 4 <= Nn) {
            float4 b4 = *(const float4*)&g_bias[n];
            float4 c4 = *(const float4*)&crow[j];
            s += fexp(c4.x + b4.x - pmv) + fexp(c4.y + b4.y - pmv)
               + fexp(c4.z + b4.z - pmv) + fexp(c4.w + b4.w - pmv);
        } else {
            for (int q = 0; q < 4; ++q)
                if (n + q < Nn) s += fexp(crow[j + q] + g_bias[n + q] - pmv);
        }
    }
    s += __shfl_xor_sync(0xffffffffu, s, 1);
    if ((tid & 1) == 0) {
        g_pm[(size_t)blockIdx.y * B_DIM + m] = pmv;
        g_ps[(size_t)blockIdx.y * B_DIM + m] = s;
    }
}

// -------------------- lse merge -------------------------------------------------
__global__ void lse_merge_kernel(int ntiles) {
    int m = blockIdx.x * 256 + threadIdx.x;
    if (m >= B_DIM) return;
    float M = -3.0e38f;
    for (int t = 0; t < ntiles; ++t) M = fmaxf(M, g_pm[(size_t)t * B_DIM + m]);
    float S = 0.f;
    for (int t = 0; t < ntiles; ++t) {
        float pm = g_pm[(size_t)t * B_DIM + m];
        if (pm > -1.0e38f) S += g_ps[(size_t)t * B_DIM + m] * fexp(pm - M);
    }
    g_L[m] = M + logf(S);
}

// -------------------- gemm2 (double-buffered) -----------------------------------
// smem per buffer: Ah,Al[128][40] (20480) + Bh,Bl[32][264] (33792) = 54272; x2 = 108544
// epilogue overlays float Cs[128][264] = 135168
#define SM2_BYTES 135168
__global__ __launch_bounds__(512) void gemm2_kernel(int Nn, int CHv) {
    extern __shared__ char sm[];
    const uint32_t sb = smem_u32(sm);
    float* Cs = (float*)sm;
    __shared__ unsigned scm[2][32];
    const int tid = threadIdx.x, wid = tid >> 5, lane = tid & 31;
    const int wm = wid & 1, wd = wid >> 1;
    const int m0 = blockIdx.x * 128;
    const int sp = blockIdx.y;
    const int ns = sp * CHv, ne = min(ns + CHv, Nn);
    if (ns >= ne) {
        const size_t pb = ((size_t)sp * B_DIM + m0) * D_DIM;
        for (int i = tid; i < 128 * D_DIM / 4; i += 512)
            *(float4*)&g_part[pb + (size_t)i * 4] = make_float4(0.f, 0.f, 0.f, 0.f);
        return;
    }
    const int nch = (ne - ns + 31) / 32;

    wmma::fragment<wmma::accumulator, 16, 16, 16, float> acc[4][2];
#pragma unroll
    for (int mi = 0; mi < 4; ++mi)
#pragma unroll
        for (int ni = 0; ni < 2; ++ni) wmma::fill_fragment(acc[mi][ni], 0.0f);

    const int r = tid >> 2, ng = (tid & 3) * 8;
    const float Lm = g_L[m0 + r];
    const float* zrow = g_z + (size_t)(m0 + r) * NPAD;
    const int rb = tid >> 4, cb = (tid & 15) * 16;
    const char* sPB  = (const char*)(g_pathi + (size_t)rb * D_DIM + cb);
    const char* sPBl = (const char*)(g_patlo + (size_t)rb * D_DIM + cb);
    const uint32_t dB = sb + rb * 528 + cb * 2;
    const uint32_t dA = sb + r * 80 + ng * 2;
    if (tid < 32) { scm[0][tid] = 0u; scm[1][tid] = 0u; }
    __syncthreads();

    // compute weights for chunk, pack into buffer, track colmax into scm[ch&1]
#define G2_WCOMP(k0v, buf, chpar) do { \
        float e[8]; \
        long nbase = (long)(k0v) + ng; \
        if (nbase + 8 <= Nn) { \
            float4 a = *(const float4*)&zrow[nbase]; \
            float4 b = *(const float4*)&zrow[nbase + 4]; \
            e[0] = fexp(a.x - Lm); e[1] = fexp(a.y - Lm); \
            e[2] = fexp(a.z - Lm); e[3] = fexp(a.w - Lm); \
            e[4] = fexp(b.x - Lm); e[5] = fexp(b.y - Lm); \
            e[6] = fexp(b.z - Lm); e[7] = fexp(b.w - Lm); \
        } else { \
            for (int j = 0; j < 8; ++j) { \
                long nn = nbase + j; \
                e[j] = (nn < Nn) ? fexp(zrow[nn] - Lm) : 0.f; \
            } \
        } \
        uint32_t h0 = pk2bf(e[0], e[1]), h1 = pk2bf(e[2], e[3]); \
        uint32_t h2 = pk2bf(e[4], e[5]), h3 = pk2bf(e[6], e[7]); \
        uint32_t d = dA + (buf) * 54272; \
        *(uint4*)(sm + (d - sb)) = make_uint4(h0, h1, h2, h3); \
        *(uint4*)(sm + (d - sb) + 10240) = make_uint4( \
            pk2bf(e[0] - wlo(h0), e[1] - whi(h0)), pk2bf(e[2] - wlo(h1), e[3] - whi(h1)), \
            pk2bf(e[4] - wlo(h2), e[5] - whi(h2)), pk2bf(e[6] - wlo(h3), e[7] - whi(h3))); \
        uint32_t cm[8]; \
        for (int j = 0; j < 8; ++j) cm[j] = __float_as_uint(e[j]); \
        for (int off = 4; off <= 16; off <<= 1) \
            for (int j = 0; j < 8; ++j) { \
                uint32_t o = __shfl_xor_sync(0xffffffffu, cm[j], off); \
                cm[j] = (o > cm[j]) ? o : cm[j]; \
            } \
        if ((lane >> 2) == 0) \
            for (int j = 0; j < 8; ++j) atomicMax(&scm[chpar][(lane & 3) * 8 + j], cm[j]); \
    } while (0)

#define G2_BISSUE(k0v, buf) do { \
        uint32_t d = dB + (buf) * 54272 + 20480; \
        long ob = (long)(k0v) * D_DIM * 2; \
        CP16(d, sPB + ob); CP16(d + 16, sPB + ob + 16); \
        CP16(d + 16896, sPBl + ob); CP16(d + 16912, sPBl + ob + 16); \
        CP_COMMIT(); } while (0)

    // prologue: chunk 0 -> buf 0
    G2_BISSUE(ns, 0);
    G2_WCOMP(ns, 0, 0);
    CP_WAIT0();
    __syncthreads();

    for (int ci = 0; ci < nch; ++ci) {
        const int cur = ci & 1;
        // flush colmax for chunk ci-1 (resides in scm[cur^1], filled before last sync)
        if (ci > 0 && tid < 32) {
            int n = ns + (ci - 1) * 32 + tid;
            unsigned v = scm[cur ^ 1][tid];
            if (n < Nn && v) atomicMax(&g_cmax[n], v);
            scm[cur ^ 1][tid] = 0u;
        }
        const bool pre = (ci + 1 < nch);
        if (pre) G2_BISSUE(ns + (ci + 1) * 32, cur ^ 1);

        const __nv_bfloat16* Ah = (const __nv_bfloat16*)(sm + cur * 54272);
        const __nv_bfloat16* Al = (const __nv_bfloat16*)(sm + cur * 54272 + 10240);
        const __nv_bfloat16* Bh = (const __nv_bfloat16*)(sm + cur * 54272 + 20480);
        const __nv_bfloat16* Bl = (const __nv_bfloat16*)(sm + cur * 54272 + 37376);
#pragma unroll
        for (int kk = 0; kk < 32; kk += 16) {
            wmma::fragment<wmma::matrix_a, 16, 16, 16, __nv_bfloat16, wmma::row_major> ah[4], al[4];
            wmma::fragment<wmma::matrix_b, 16, 16, 16, __nv_bfloat16, wmma::row_major> bh[2], bl[2];
#pragma unroll
            for (int mi = 0; mi < 4; ++mi) {
                wmma::load_matrix_sync(ah[mi], &Ah[(wm * 64 + mi * 16) * 40 + kk], 40);
                wmma::load_matrix_sync(al[mi], &Al[(wm * 64 + mi * 16) * 40 + kk], 40);
            }
#pragma unroll
            for (int ni = 0; ni < 2; ++ni) {
                wmma::load_matrix_sync(bh[ni], &Bh[kk * 264 + wd * 32 + ni * 16], 264);
                wmma::load_matrix_sync(bl[ni], &Bl[kk * 264 + wd * 32 + ni * 16], 264);
            }
#pragma unroll
            for (int mi = 0; mi < 4; ++mi)
#pragma unroll
                for (int ni = 0; ni < 2; ++ni) {
                    wmma::mma_sync(acc[mi][ni], ah[mi], bh[ni], acc[mi][ni]);
                    wmma::mma_sync(acc[mi][ni], al[mi], bh[ni], acc[mi][ni]);
                    wmma::mma_sync(acc[mi][ni], ah[mi], bl[ni], acc[mi][ni]);
                }
        }
        if (pre) {
            G2_WCOMP(ns + (ci + 1) * 32, cur ^ 1, cur ^ 1);
            CP_WAIT0();
        }
        __syncthreads();
    }
    // flush last chunk's colmax (scm[(nch-1)&1])
    if (tid < 32) {
        int n = ns + (nch - 1) * 32 + tid;
        unsigned v = scm[(nch - 1) & 1][tid];
        if (n < Nn && v) atomicMax(&g_cmax[n], v);
    }

#pragma unroll
    for (int mi = 0; mi < 4; ++mi)
#pragma unroll
        for (int ni = 0; ni < 2; ++ni)
            wmma::store_matrix_sync(&Cs[(wm * 64 + mi * 16) * 264 + wd * 32 + ni * 16],
                                    acc[mi][ni], 264, wmma::mem_row_major);
    __syncthreads();
    const int rr = tid >> 2, cgr = (tid & 3) * 64;
    const size_t ob = ((size_t)sp * B_DIM + m0 + rr) * D_DIM + cgr;
#pragma unroll
    for (int j = 0; j < 64; j += 4)
        *(float4*)&g_part[ob + j] = *(const float4*)&Cs[rr * 264 + cgr + j];
}

// -------------------- reductions / output --------------------------------------
__global__ void reduce_ret_kernel(float* __restrict__ out) {
    size_t i = (size_t)blockIdx.x * 256 + threadIdx.x;
    float4 s = make_float4(0.f, 0.f, 0.f, 0.f);
    for (int sp = 0; sp < NSPLIT; ++sp) {
        float4 v = *(const float4*)&g_part[(size_t)sp * (B_DIM * D_DIM) + i * 4];
        s.x += v.x; s.y += v.y; s.z += v.z; s.w += v.w;
    }
    *(float4*)&out[i * 4] = s;
}

__global__ void depths_kernel(const float* __restrict__ depths,
                              float* __restrict__ out, int Nn) {
    int i = blockIdx.x * 256 + threadIdx.x;
    if (i >= Nn) return;
    float d = depths[i];
    float maxw = __uint_as_float(g_cmax[i]);
    float dom = log1pf(d) / fmaxf(__int_as_float(g_logdmax), 1e-8f);
    float rate = 0.01f * (1.0f - 0.7f * dom);
    out[B_DIM * D_DIM + i] = d + ((maxw > 0.1f) ? rate * maxw : 0.0f);
}

extern "C" void kernel_launch(void* const* d_in, const int* in_sizes, int n_in,
                              void* d_out, int out_size) {
    const float* state  = (const float*)d_in[0];
    const float* W      = (const float*)d_in[1];
    const float* pat    = (const float*)d_in[2];
    const float* depths = (const float*)d_in[3];
    const float* gate   = (const float*)d_in[4];
    float* out = (float*)d_out;
    const int Nn = in_sizes[3];

    cudaFuncSetAttribute(gemm1_kernel, cudaFuncAttributeMaxDynamicSharedMemorySize, SM1_BYTES);
    cudaFuncSetAttribute(gemm2_kernel, cudaFuncAttributeMaxDynamicSharedMemorySize, SM2_BYTES);

    const int nbN = (Nn + 255) / 256;
    init_kernel<<<nbN, 256>>>(Nn);
    proj_kernel<<<B_DIM, 256>>>(state, W);
    bias_kernel<<<nbN, 256>>>(depths, gate, Nn);
    patprep_kernel<<<(NPAD * D_DIM / 4) / 256, 256>>>(pat, Nn);

    const int ntiles = (Nn + 127) / 128;
    gemm1_kernel<<<dim3(B_DIM / 128, ntiles), 256, SM1_BYTES>>>(Nn);
    lse_merge_kernel<<<B_DIM / 256, 256>>>(ntiles);

    const int CHv = ((Nn + NSPLIT * 32 - 1) / (NSPLIT * 32)) * 32;
    gemm2_kernel<<<dim3(B_DIM / 128, NSPLIT), 512, SM2_BYTES>>>(Nn, CHv);

    reduce_ret_kernel<<<(B_DIM * D_DIM / 4) / 256, 256>>>(out);
    depths_kernel<<<nbN, 256>>>(depths, out, Nn);
}

// round 7
// speedup vs baseline: 3.6814x; 1.2882x over previous
#include <cuda_runtime.h>
#include <cuda_fp16.h>
#include <mma.h>
#include <math.h>
#include <stdint.h>

using namespace nvcuda;

#define B_DIM 1024
#define D_DIM 256
#define NPAD  100352
#define NSPLIT 37
#define NT1 392            // NPAD / 256

__device__ __half g_projh[B_DIM * D_DIM];
__device__ __half g_projl[B_DIM * D_DIM];
__device__ float g_bias[NPAD];
__device__ float g_z[(size_t)B_DIM * NPAD];
__device__ float g_L[B_DIM];
__device__ float g_pm[(size_t)NT1 * B_DIM];
__device__ float g_ps[(size_t)NT1 * B_DIM];
__device__ __half g_patf[(size_t)NPAD * D_DIM];
__device__ float g_part[(size_t)NSPLIT * B_DIM * D_DIM];
__device__ unsigned g_cmax[NPAD];
__device__ int g_logdmax;

// fast exp on FMA pipe (rel err ~3e-6)
__device__ __forceinline__ float fexp(float x) {
    float y = fmaxf(x * 1.44269504088896f, -126.0f);
    float k = rintf(y);
    float f = y - k;
    float p = 1.3333558146e-3f;
    p = fmaf(p, f, 9.6181291076e-3f);
    p = fmaf(p, f, 5.5504108664e-2f);
    p = fmaf(p, f, 2.4022650696e-1f);
    p = fmaf(p, f, 6.9314718056e-1f);
    p = fmaf(p, f, 1.0f);
    return p * __int_as_float(((int)k + 127) << 23);
}
__device__ __forceinline__ uint32_t pk2h(float lo, float hi) {
    uint32_t d; asm("cvt.rn.f16x2.f32 %0, %1, %2;" : "=r"(d) : "f"(hi), "f"(lo)); return d;
}
__device__ __forceinline__ float2 up2h(uint32_t p) {
    __half2 h = *reinterpret_cast<__half2*>(&p);
    return __half22float2(h);
}
__device__ __forceinline__ uint32_t smem_u32(const void* p) {
    uint32_t a;
    asm("{ .reg .u64 t; cvta.to.shared.u64 t, %1; cvt.u32.u64 %0, t; }" : "=r"(a) : "l"(p));
    return a;
}
#define CP16(dst, src) \
    asm volatile("cp.async.cg.shared.global [%0], [%1], 16;" :: "r"(dst), "l"(src))
#define CP_COMMIT() asm volatile("cp.async.commit_group;" ::: "memory")
#define CP_WAIT0()  asm volatile("cp.async.wait_group 0;" ::: "memory")

// -------------------- prep ----------------------------------------------------
__global__ void init_kernel(int Nn) {
    int i = blockIdx.x * blockDim.x + threadIdx.x;
    if (i < Nn) g_cmax[i] = 0u;
    if (i == 0) g_logdmax = 0;
}

__global__ void proj_kernel(const float* __restrict__ state, const float* __restrict__ W) {
    __shared__ float s[D_DIM];
    int b = blockIdx.x, j = threadIdx.x;
    s[j] = state[b * D_DIM + j];
    __syncthreads();
    const float* wr = W + j * D_DIM;
    float acc = 0.f;
#pragma unroll 16
    for (int d = 0; d < D_DIM; ++d) acc = fmaf(s[d], wr[d], acc);
    __half h = __float2half_rn(acc);
    g_projh[b * D_DIM + j] = h;
    g_projl[b * D_DIM + j] = __float2half_rn(acc - __half2float(h));
}

__global__ void bias_kernel(const float* __restrict__ depths,
                            const float* __restrict__ gate, int Nn) {
    int i = blockIdx.x * 256 + threadIdx.x;
    float lv = 0.f;
    if (i < Nn) {
        float d = depths[i], g = gate[i];
        g_bias[i] = logf(fmaxf(d, 1e-8f)) + logf(fmaxf(g, 1e-8f));
        lv = log1pf(d);
    }
    __shared__ float red[256];
    red[threadIdx.x] = lv;
    __syncthreads();
#pragma unroll
    for (int o = 128; o > 0; o >>= 1) {
        if (threadIdx.x < o) red[threadIdx.x] = fmaxf(red[threadIdx.x], red[threadIdx.x + o]);
        __syncthreads();
    }
    if (threadIdx.x == 0) atomicMax(&g_logdmax, __float_as_int(red[0]));
}

__global__ void patprep_kernel(const float* __restrict__ pat, int Nn) {
    long i = (long)blockIdx.x * 256 + threadIdx.x;
    long e0 = i * 4;
    long n = e0 >> 8;
    float4 v = (n < Nn) ? *(const float4*)&pat[e0] : make_float4(0.f, 0.f, 0.f, 0.f);
    *(uint2*)&g_patf[e0] = make_uint2(pk2h(v.x, v.y), pk2h(v.z, v.w));
}

// -------------------- gemm1: z = proj @ pat^T + bias (fp16 2-pass) -------------
// CTA tile 128(M) x 256(N), k-chunks of 32, double-buffered cp.async.
// smem/stage: Ah[128][40] 10240 + Al 10240 + B[256][40] 20480 = 40960; x2 = 81920
// epilogue overlay: float Cs[128][264] = 135168
#define SM1_BYTES 135168
__global__ __launch_bounds__(512) void gemm1_kernel(int Nn) {
    extern __shared__ char sm[];
    const uint32_t sb = smem_u32(sm);
    float* Cs = (float*)sm;
    const int tid = threadIdx.x, wid = tid >> 5;
    const int wm = wid >> 2, wn = wid & 3;              // 4 x 4 warps, tile 32 x 64
    const int m0 = blockIdx.x * 128;
    const long n0 = (long)blockIdx.y * 256;

    wmma::fragment<wmma::accumulator, 16, 16, 16, float> acc[2][4];
#pragma unroll
    for (int mi = 0; mi < 2; ++mi)
#pragma unroll
        for (int ni = 0; ni < 4; ++ni) wmma::fill_fragment(acc[mi][ni], 0.0f);

    const int ar = tid >> 2, ac = (tid & 3) * 8;        // A: 16B per thread
    const int br = tid >> 1, bc = (tid & 1) * 16;       // B: 32B per thread
    const char* sAh = (const char*)(g_projh + (size_t)(m0 + ar) * D_DIM + ac);
    const char* sAl = (const char*)(g_projl + (size_t)(m0 + ar) * D_DIM + ac);
    const char* sB  = (const char*)(g_patf + (n0 + br) * D_DIM + bc);
    const uint32_t dA = sb + ar * 80 + ac * 2;
    const uint32_t dB = sb + 20480 + br * 80 + bc * 2;

#define G1_ISSUE(c, buf) do { \
        long ob = (long)(c) * 64; \
        uint32_t da = dA + (buf) * 40960, db = dB + (buf) * 40960; \
        CP16(da, sAh + ob); CP16(da + 10240, sAl + ob); \
        CP16(db, sB + ob); CP16(db + 16, sB + ob + 16); \
        CP_COMMIT(); } while (0)

    G1_ISSUE(0, 0);
    CP_WAIT0();
    __syncthreads();

    for (int c = 0; c < 8; ++c) {
        const int cur = c & 1;
        if (c < 7) G1_ISSUE(c + 1, cur ^ 1);
        const __half* Ah = (const __half*)(sm + cur * 40960);
        const __half* Al = (const __half*)(sm + cur * 40960 + 10240);
        const __half* Bs = (const __half*)(sm + cur * 40960 + 20480);
#pragma unroll
        for (int kk = 0; kk < 32; kk += 16) {
            wmma::fragment<wmma::matrix_a, 16, 16, 16, __half, wmma::row_major> ah[2], al[2];
            wmma::fragment<wmma::matrix_b, 16, 16, 16, __half, wmma::col_major> bh[4];
#pragma unroll
            for (int mi = 0; mi < 2; ++mi) {
                wmma::load_matrix_sync(ah[mi], &Ah[(wm * 32 + mi * 16) * 40 + kk], 40);
                wmma::load_matrix_sync(al[mi], &Al[(wm * 32 + mi * 16) * 40 + kk], 40);
            }
#pragma unroll
            for (int ni = 0; ni < 4; ++ni)
                wmma::load_matrix_sync(bh[ni], &Bs[(wn * 64 + ni * 16) * 40 + kk], 40);
#pragma unroll
            for (int mi = 0; mi < 2; ++mi)
#pragma unroll
                for (int ni = 0; ni < 4; ++ni) {
                    wmma::mma_sync(acc[mi][ni], ah[mi], bh[ni], acc[mi][ni]);
                    wmma::mma_sync(acc[mi][ni], al[mi], bh[ni], acc[mi][ni]);
                }
        }
        if (c < 7) CP_WAIT0();
        __syncthreads();
    }

#pragma unroll
    for (int mi = 0; mi < 2; ++mi)
#pragma unroll
        for (int ni = 0; ni < 4; ++ni)
            wmma::store_matrix_sync(&Cs[(wm * 32 + mi * 16) * 264 + wn * 64 + ni * 16],
                                    acc[mi][ni], 264, wmma::mem_row_major);
    __syncthreads();

    // epilogue: add bias, write z, per-tile row max + sum(exp)
    const int r2 = tid >> 2, hc = (tid & 3) * 64;
    const int m = m0 + r2;
    float* zrow = g_z + (size_t)m * NPAD;
    const float* crow = Cs + r2 * 264 + hc;
    float vmax = -3.0e38f;
#pragma unroll
    for (int j = 0; j < 64; j += 4) {
        long n = n0 + hc + j;
        if (n + 4 <= Nn) {
            float4 b4 = *(const float4*)&g_bias[n];
            float4 c4 = *(const float4*)&crow[j];
            float4 o = make_float4(c4.x + b4.x, c4.y + b4.y, c4.z + b4.z, c4.w + b4.w);
            vmax = fmaxf(vmax, fmaxf(fmaxf(o.x, o.y), fmaxf(o.z, o.w)));
            *(float4*)&zrow[n] = o;
        } else {
            for (int q = 0; q < 4; ++q)
                if (n + q < Nn) {
                    float v = crow[j + q] + g_bias[n + q];
                    vmax = fmaxf(vmax, v);
                    zrow[n + q] = v;
                }
        }
    }
    float pmv = fmaxf(vmax, __shfl_xor_sync(0xffffffffu, vmax, 1));
    pmv = fmaxf(pmv, __shfl_xor_sync(0xffffffffu, pmv, 2));
    float s = 0.f;
#pragma unroll
    for (int j = 0; j < 64; j += 4) {
        long n = n0 + hc + j;
        if (n + 4 <= Nn) {
            float4 b4 = *(const float4*)&g_bias[n];
            float4 c4 = *(const float4*)&crow[j];
            s += fexp(c4.x + b4.x - pmv) + fexp(c4.y + b4.y - pmv)
               + fexp(c4.z + b4.z - pmv) + fexp(c4.w + b4.w - pmv);
        } else {
            for (int q = 0; q < 4; ++q)
                if (n + q < Nn) s += fexp(crow[j + q] + g_bias[n + q] - pmv);
        }
    }
    s += __shfl_xor_sync(0xffffffffu, s, 1);
    s += __shfl_xor_sync(0xffffffffu, s, 2);
    if ((tid & 3) == 0) {
        g_pm[(size_t)blockIdx.y * B_DIM + m] = pmv;
        g_ps[(size_t)blockIdx.y * B_DIM + m] = s;
    }
}

// -------------------- lse merge -------------------------------------------------
__global__ void lse_merge_kernel(int ntiles) {
    int m = blockIdx.x * 256 + threadIdx.x;
    if (m >= B_DIM) return;
    float M = -3.0e38f;
    for (int t = 0; t < ntiles; ++t) M = fmaxf(M, g_pm[(size_t)t * B_DIM + m]);
    float S = 0.f;
    for (int t = 0; t < ntiles; ++t) {
        float pm = g_pm[(size_t)t * B_DIM + m];
        if (pm > -1.0e38f) S += g_ps[(size_t)t * B_DIM + m] * fexp(pm - M);
    }
    g_L[m] = M + logf(S);
}

// -------------------- gemm2: part = exp(z-L) @ pat + colmax (fp16 2-pass) ------
// smem/stage: Ah[128][40] 10240 + Al 10240 + B[32][264] 16896 = 37376; x2 = 74752
// epilogue overlay: float Cs[128][264] = 135168
#define SM2_BYTES 135168
__global__ __launch_bounds__(512) void gemm2_kernel(int Nn, int CHv) {
    extern __shared__ char sm[];
    const uint32_t sb = smem_u32(sm);
    float* Cs = (float*)sm;
    __shared__ unsigned scm[2][32];
    const int tid = threadIdx.x, wid = tid >> 5, lane = tid & 31;
    const int wm = wid >> 2, wd = wid & 3;              // 4 x 4 warps, tile 32 x 64
    const int m0 = blockIdx.x * 128;
    const int sp = blockIdx.y;
    const int ns = sp * CHv, ne = min(ns + CHv, Nn);
    if (ns >= ne) {
        const size_t pb = ((size_t)sp * B_DIM + m0) * D_DIM;
        for (int i = tid; i < 128 * D_DIM / 4; i += 512)
            *(float4*)&g_part[pb + (size_t)i * 4] = make_float4(0.f, 0.f, 0.f, 0.f);
        return;
    }
    const int nch = (ne - ns + 31) / 32;

    wmma::fragment<wmma::accumulator, 16, 16, 16, float> acc[2][4];
#pragma unroll
    for (int mi = 0; mi < 2; ++mi)
#pragma unroll
        for (int ni = 0; ni < 4; ++ni) wmma::fill_fragment(acc[mi][ni], 0.0f);

    const int r = tid >> 2, ng = (tid & 3) * 8;
    const float Lm = g_L[m0 + r];
    const float* zrow = g_z + (size_t)(m0 + r) * NPAD;
    const uint32_t dA = sb + r * 80 + ng * 2;
    if (tid < 32) { scm[0][tid] = 0u; scm[1][tid] = 0u; }
    __syncthreads();

#define G2_WCOMP(k0v, buf, chpar) do { \
        float e[8]; \
        long nbase = (long)(k0v) + ng; \
        if (nbase + 8 <= Nn) { \
            float4 a = *(const float4*)&zrow[nbase]; \
            float4 b = *(const float4*)&zrow[nbase + 4]; \
            e[0] = fexp(a.x - Lm); e[1] = fexp(a.y - Lm); \
            e[2] = fexp(a.z - Lm); e[3] = fexp(a.w - Lm); \
            e[4] = fexp(b.x - Lm); e[5] = fexp(b.y - Lm); \
            e[6] = fexp(b.z - Lm); e[7] = fexp(b.w - Lm); \
        } else { \
            for (int j = 0; j < 8; ++j) { \
                long nn = nbase + j; \
                e[j] = (nn < Nn) ? fexp(zrow[nn] - Lm) : 0.f; \
            } \
        } \
        uint32_t h0 = pk2h(e[0], e[1]), h1 = pk2h(e[2], e[3]); \
        uint32_t h2 = pk2h(e[4], e[5]), h3 = pk2h(e[6], e[7]); \
        float2 f0 = up2h(h0), f1 = up2h(h1), f2 = up2h(h2), f3 = up2h(h3); \
        uint32_t doff = dA + (buf) * 37376 - sb; \
        *(uint4*)(sm + doff) = make_uint4(h0, h1, h2, h3); \
        *(uint4*)(sm + doff + 10240) = make_uint4( \
            pk2h(e[0] - f0.x, e[1] - f0.y), pk2h(e[2] - f1.x, e[3] - f1.y), \
            pk2h(e[4] - f2.x, e[5] - f2.y), pk2h(e[6] - f3.x, e[7] - f3.y)); \
        uint32_t cm[8]; \
        for (int j = 0; j < 8; ++j) cm[j] = __float_as_uint(e[j]); \
        for (int off = 4; off <= 16; off <<= 1) \
            for (int j = 0; j < 8; ++j) { \
                uint32_t o = __shfl_xor_sync(0xffffffffu, cm[j], off); \
                cm[j] = (o > cm[j]) ? o : cm[j]; \
            } \
        if ((lane >> 2) == 0) \
            for (int j = 0; j < 8; ++j) atomicMax(&scm[chpar][(lane & 3) * 8 + j], cm[j]); \
    } while (0)

#define G2_BISSUE(k0v, buf) do { \
        int s0 = tid, s1 = tid + 512; \
        uint32_t base = sb + (buf) * 37376 + 20480; \
        const char* psrc = (const char*)(g_patf + (size_t)(k0v) * D_DIM); \
        CP16(base + (s0 >> 5) * 528 + (s0 & 31) * 16, psrc + (s0 >> 5) * 512 + (s0 & 31) * 16); \
        CP16(base + (s1 >> 5) * 528 + (s1 & 31) * 16, psrc + (s1 >> 5) * 512 + (s1 & 31) * 16); \
        CP_COMMIT(); } while (0)

    G2_BISSUE(ns, 0);
    G2_WCOMP(ns, 0, 0);
    CP_WAIT0();
    __syncthreads();

    for (int ci = 0; ci < nch; ++ci) {
        const int cur = ci & 1;
        if (ci > 0 && tid < 32) {
            int n = ns + (ci - 1) * 32 + tid;
            unsigned v = scm[cur ^ 1][tid];
            if (n < Nn && v) atomicMax(&g_cmax[n], v);
            scm[cur ^ 1][tid] = 0u;
        }
        const bool pre = (ci + 1 < nch);
        if (pre) G2_BISSUE(ns + (ci + 1) * 32, cur ^ 1);

        const __half* Ah = (const __half*)(sm + cur * 37376);
        const __half* Al = (const __half*)(sm + cur * 37376 + 10240);
        const __half* Bs = (const __half*)(sm + cur * 37376 + 20480);
#pragma unroll
        for (int kk = 0; kk < 32; kk += 16) {
            wmma::fragment<wmma::matrix_a, 16, 16, 16, __half, wmma::row_major> ah[2], al[2];
            wmma::fragment<wmma::matrix_b, 16, 16, 16, __half, wmma::row_major> bh[4];
#pragma unroll
            for (int mi = 0; mi < 2; ++mi) {
                wmma::load_matrix_sync(ah[mi], &Ah[(wm * 32 + mi * 16) * 40 + kk], 40);
                wmma::load_matrix_sync(al[mi], &Al[(wm * 32 + mi * 16) * 40 + kk], 40);
            }
#pragma unroll
            for (int ni = 0; ni < 4; ++ni)
                wmma::load_matrix_sync(bh[ni], &Bs[kk * 264 + wd * 64 + ni * 16], 264);
#pragma unroll
            for (int mi = 0; mi < 2; ++mi)
#pragma unroll
                for (int ni = 0; ni < 4; ++ni) {
                    wmma::mma_sync(acc[mi][ni], ah[mi], bh[ni], acc[mi][ni]);
                    wmma::mma_sync(acc[mi][ni], al[mi], bh[ni], acc[mi][ni]);
                }
        }
        if (pre) {
            G2_WCOMP(ns + (ci + 1) * 32, cur ^ 1, cur ^ 1);
            CP_WAIT0();
        }
        __syncthreads();
    }
    if (tid < 32) {
        int n = ns + (nch - 1) * 32 + tid;
        unsigned v = scm[(nch - 1) & 1][tid];
        if (n < Nn && v) atomicMax(&g_cmax[n], v);
    }

#pragma unroll
    for (int mi = 0; mi < 2; ++mi)
#pragma unroll
        for (int ni = 0; ni < 4; ++ni)
            wmma::store_matrix_sync(&Cs[(wm * 32 + mi * 16) * 264 + wd * 64 + ni * 16],
                                    acc[mi][ni], 264, wmma::mem_row_major);
    __syncthreads();
    const int rr = tid >> 2, cgr = (tid & 3) * 64;
    const size_t ob = ((size_t)sp * B_DIM + m0 + rr) * D_DIM + cgr;
#pragma unroll
    for (int j = 0; j < 64; j += 4)
        *(float4*)&g_part[ob + j] = *(const float4*)&Cs[rr * 264 + cgr + j];
}

// -------------------- reductions / output --------------------------------------
__global__ void reduce_ret_kernel(float* __restrict__ out) {
    size_t i = (size_t)blockIdx.x * 256 + threadIdx.x;
    float4 s = make_float4(0.f, 0.f, 0.f, 0.f);
    for (int sp = 0; sp < NSPLIT; ++sp) {
        float4 v = *(const float4*)&g_part[(size_t)sp * (B_DIM * D_DIM) + i * 4];
        s.x += v.x; s.y += v.y; s.z += v.z; s.w += v.w;
    }
    *(float4*)&out[i * 4] = s;
}

__global__ void depths_kernel(const float* __restrict__ depths,
                              float* __restrict__ out, int Nn) {
    int i = blockIdx.x * 256 + threadIdx.x;
    if (i >= Nn) return;
    float d = depths[i];
    float maxw = __uint_as_float(g_cmax[i]);
    float dom = log1pf(d) / fmaxf(__int_as_float(g_logdmax), 1e-8f);
    float rate = 0.01f * (1.0f - 0.7f * dom);
    out[B_DIM * D_DIM + i] = d + ((maxw > 0.1f) ? rate * maxw : 0.0f);
}

extern "C" void kernel_launch(void* const* d_in, const int* in_sizes, int n_in,
                              void* d_out, int out_size) {
    const float* state  = (const float*)d_in[0];
    const float* W      = (const float*)d_in[1];
    const float* pat    = (const float*)d_in[2];
    const float* depths = (const float*)d_in[3];
    const float* gate   = (const float*)d_in[4];
    float* out = (float*)d_out;
    const int Nn = in_sizes[3];

    cudaFuncSetAttribute(gemm1_kernel, cudaFuncAttributeMaxDynamicSharedMemorySize, SM1_BYTES);
    cudaFuncSetAttribute(gemm2_kernel, cudaFuncAttributeMaxDynamicSharedMemorySize, SM2_BYTES);

    const int nbN = (Nn + 255) / 256;
    init_kernel<<<nbN, 256>>>(Nn);
    proj_kernel<<<B_DIM, 256>>>(state, W);
    bias_kernel<<<nbN, 256>>>(depths, gate, Nn);
    patprep_kernel<<<(NPAD * D_DIM / 4) / 256, 256>>>(pat, Nn);

    gemm1_kernel<<<dim3(B_DIM / 128, NT1), 512, SM1_BYTES>>>(Nn);
    lse_merge_kernel<<<B_DIM / 256, 256>>>(NT1);

    const int CHv = ((Nn + NSPLIT * 32 - 1) / (NSPLIT * 32)) * 32;
    gemm2_kernel<<<dim3(B_DIM / 128, NSPLIT), 512, SM2_BYTES>>>(Nn, CHv);

    reduce_ret_kernel<<<(B_DIM * D_DIM / 4) / 256, 256>>>(out);
    depths_kernel<<<nbN, 256>>>(depths, out, Nn);
}

// round 8
// speedup vs baseline: 4.2955x; 1.1668x over previous
#include <cuda_runtime.h>
#include <cuda_fp16.h>
#include <mma.h>
#include <math.h>
#include <stdint.h>

using namespace nvcuda;

#define B_DIM 1024
#define D_DIM 256
#define NPAD  100352
#define NSPLIT 37
#define NT1 392            // NPAD / 256

__device__ __half g_projh[B_DIM * D_DIM];
__device__ float g_bias[NPAD];
__device__ float g_z[(size_t)B_DIM * NPAD];
__device__ float g_L[B_DIM];
__device__ float g_pm[(size_t)NT1 * B_DIM];
__device__ float g_ps[(size_t)NT1 * B_DIM];
__device__ __half g_patf[(size_t)NPAD * D_DIM];
__device__ float g_part[(size_t)NSPLIT * B_DIM * D_DIM];
__device__ unsigned g_cmax[NPAD];
__device__ int g_logdmax;

// fast exp on FMA pipe (rel err ~3e-6)
__device__ __forceinline__ float fexp(float x) {
    float y = fmaxf(x * 1.44269504088896f, -126.0f);
    float k = rintf(y);
    float f = y - k;
    float p = 1.3333558146e-3f;
    p = fmaf(p, f, 9.6181291076e-3f);
    p = fmaf(p, f, 5.5504108664e-2f);
    p = fmaf(p, f, 2.4022650696e-1f);
    p = fmaf(p, f, 6.9314718056e-1f);
    p = fmaf(p, f, 1.0f);
    return p * __int_as_float(((int)k + 127) << 23);
}
__device__ __forceinline__ uint32_t pk2h(float lo, float hi) {
    uint32_t d; asm("cvt.rn.f16x2.f32 %0, %1, %2;" : "=r"(d) : "f"(hi), "f"(lo)); return d;
}
__device__ __forceinline__ uint32_t smem_u32(const void* p) {
    uint32_t a;
    asm("{ .reg .u64 t; cvta.to.shared.u64 t, %1; cvt.u32.u64 %0, t; }" : "=r"(a) : "l"(p));
    return a;
}
#define CP16(dst, src) \
    asm volatile("cp.async.cg.shared.global [%0], [%1], 16;" :: "r"(dst), "l"(src))
#define CP_COMMIT() asm volatile("cp.async.commit_group;" ::: "memory")
#define CP_WAIT0()  asm volatile("cp.async.wait_group 0;" ::: "memory")

// -------------------- prep ----------------------------------------------------
__global__ void init_kernel(int Nn) {
    int i = blockIdx.x * blockDim.x + threadIdx.x;
    if (i < Nn) g_cmax[i] = 0u;
    if (i == 0) g_logdmax = 0;
}

__global__ void proj_kernel(const float* __restrict__ state, const float* __restrict__ W) {
    __shared__ float s[D_DIM];
    int b = blockIdx.x, j = threadIdx.x;
    s[j] = state[b * D_DIM + j];
    __syncthreads();
    const float* wr = W + j * D_DIM;
    float acc = 0.f;
#pragma unroll 16
    for (int d = 0; d < D_DIM; ++d) acc = fmaf(s[d], wr[d], acc);
    g_projh[b * D_DIM + j] = __float2half_rn(acc);
}

__global__ void bias_kernel(const float* __restrict__ depths,
                            const float* __restrict__ gate, int Nn) {
    int i = blockIdx.x * 256 + threadIdx.x;
    float lv = 0.f;
    if (i < Nn) {
        float d = depths[i], g = gate[i];
        g_bias[i] = logf(fmaxf(d, 1e-8f)) + logf(fmaxf(g, 1e-8f));
        lv = log1pf(d);
    }
    __shared__ float red[256];
    red[threadIdx.x] = lv;
    __syncthreads();
#pragma unroll
    for (int o = 128; o > 0; o >>= 1) {
        if (threadIdx.x < o) red[threadIdx.x] = fmaxf(red[threadIdx.x], red[threadIdx.x + o]);
        __syncthreads();
    }
    if (threadIdx.x == 0) atomicMax(&g_logdmax, __float_as_int(red[0]));
}

__global__ void patprep_kernel(const float* __restrict__ pat, int Nn) {
    long i = (long)blockIdx.x * 256 + threadIdx.x;
    long e0 = i * 4;
    long n = e0 >> 8;
    float4 v = (n < Nn) ? *(const float4*)&pat[e0] : make_float4(0.f, 0.f, 0.f, 0.f);
    *(uint2*)&g_patf[e0] = make_uint2(pk2h(v.x, v.y), pk2h(v.z, v.w));
}

// -------------------- gemm1: z = proj @ pat^T + bias (fp16 single-pass) -------
// CTA tile 128(M) x 256(N), k-chunks of 32, double-buffered cp.async.
// smem/stage: A[128][40] 10240 + B[256][40] 20480 = 30720; x2 = 61440
// epilogue overlay: float Cs[128][264] = 135168
#define SM1_BYTES 135168
__global__ __launch_bounds__(512) void gemm1_kernel(int Nn) {
    extern __shared__ char sm[];
    const uint32_t sb = smem_u32(sm);
    float* Cs = (float*)sm;
    const int tid = threadIdx.x, wid = tid >> 5;
    const int wm = wid >> 2, wn = wid & 3;              // 4 x 4 warps, tile 32 x 64
    const int m0 = blockIdx.x * 128;
    const long n0 = (long)blockIdx.y * 256;

    wmma::fragment<wmma::accumulator, 16, 16, 16, float> acc[2][4];
#pragma unroll
    for (int mi = 0; mi < 2; ++mi)
#pragma unroll
        for (int ni = 0; ni < 4; ++ni) wmma::fill_fragment(acc[mi][ni], 0.0f);

    const int ar = tid >> 2, ac = (tid & 3) * 8;        // A: 16B per thread
    const int br = tid >> 1, bc = (tid & 1) * 16;       // B: 32B per thread
    const char* sAh = (const char*)(g_projh + (size_t)(m0 + ar) * D_DIM + ac);
    const char* sB  = (const char*)(g_patf + (n0 + br) * D_DIM + bc);
    const uint32_t dA = sb + ar * 80 + ac * 2;
    const uint32_t dB = sb + 10240 + br * 80 + bc * 2;

#define G1_ISSUE(c, buf) do { \
        long ob = (long)(c) * 64; \
        uint32_t da = dA + (buf) * 30720, db = dB + (buf) * 30720; \
        CP16(da, sAh + ob); \
        CP16(db, sB + ob); CP16(db + 16, sB + ob + 16); \
        CP_COMMIT(); } while (0)

    G1_ISSUE(0, 0);
    CP_WAIT0();
    __syncthreads();

    for (int c = 0; c < 8; ++c) {
        const int cur = c & 1;
        if (c < 7) G1_ISSUE(c + 1, cur ^ 1);
        const __half* Ah = (const __half*)(sm + cur * 30720);
        const __half* Bs = (const __half*)(sm + cur * 30720 + 10240);
#pragma unroll
        for (int kk = 0; kk < 32; kk += 16) {
            wmma::fragment<wmma::matrix_a, 16, 16, 16, __half, wmma::row_major> ah[2];
            wmma::fragment<wmma::matrix_b, 16, 16, 16, __half, wmma::col_major> bh[4];
#pragma unroll
            for (int mi = 0; mi < 2; ++mi)
                wmma::load_matrix_sync(ah[mi], &Ah[(wm * 32 + mi * 16) * 40 + kk], 40);
#pragma unroll
            for (int ni = 0; ni < 4; ++ni)
                wmma::load_matrix_sync(bh[ni], &Bs[(wn * 64 + ni * 16) * 40 + kk], 40);
#pragma unroll
            for (int mi = 0; mi < 2; ++mi)
#pragma unroll
                for (int ni = 0; ni < 4; ++ni)
                    wmma::mma_sync(acc[mi][ni], ah[mi], bh[ni], acc[mi][ni]);
        }
        if (c < 7) CP_WAIT0();
        __syncthreads();
    }

#pragma unroll
    for (int mi = 0; mi < 2; ++mi)
#pragma unroll
        for (int ni = 0; ni < 4; ++ni)
            wmma::store_matrix_sync(&Cs[(wm * 32 + mi * 16) * 264 + wn * 64 + ni * 16],
                                    acc[mi][ni], 264, wmma::mem_row_major);
    __syncthreads();

    // epilogue: add bias, write z, per-tile row max + sum(exp)
    const int r2 = tid >> 2, hc = (tid & 3) * 64;
    const int m = m0 + r2;
    float* zrow = g_z + (size_t)m * NPAD;
    const float* crow = Cs + r2 * 264 + hc;
    float vmax = -3.0e38f;
#pragma unroll
    for (int j = 0; j < 64; j += 4) {
        long n = n0 + hc + j;
        if (n + 4 <= Nn) {
            float4 b4 = *(const float4*)&g_bias[n];
            float4 c4 = *(const float4*)&crow[j];
            float4 o = make_float4(c4.x + b4.x, c4.y + b4.y, c4.z + b4.z, c4.w + b4.w);
            vmax = fmaxf(vmax, fmaxf(fmaxf(o.x, o.y), fmaxf(o.z, o.w)));
            *(float4*)&zrow[n] = o;
        } else {
            for (int q = 0; q < 4; ++q)
                if (n + q < Nn) {
                    float v = crow[j + q] + g_bias[n + q];
                    vmax = fmaxf(vmax, v);
                    zrow[n + q] = v;
                }
        }
    }
    float pmv = fmaxf(vmax, __shfl_xor_sync(0xffffffffu, vmax, 1));
    pmv = fmaxf(pmv, __shfl_xor_sync(0xffffffffu, pmv, 2));
    float s = 0.f;
#pragma unroll
    for (int j = 0; j < 64; j += 4) {
        long n = n0 + hc + j;
        if (n + 4 <= Nn) {
            float4 b4 = *(const float4*)&g_bias[n];
            float4 c4 = *(const float4*)&crow[j];
            s += fexp(c4.x + b4.x - pmv) + fexp(c4.y + b4.y - pmv)
               + fexp(c4.z + b4.z - pmv) + fexp(c4.w + b4.w - pmv);
        } else {
            for (int q = 0; q < 4; ++q)
                if (n + q < Nn) s += fexp(crow[j + q] + g_bias[n + q] - pmv);
        }
    }
    s += __shfl_xor_sync(0xffffffffu, s, 1);
    s += __shfl_xor_sync(0xffffffffu, s, 2);
    if ((tid & 3) == 0) {
        g_pm[(size_t)blockIdx.y * B_DIM + m] = pmv;
        g_ps[(size_t)blockIdx.y * B_DIM + m] = s;
    }
}

// -------------------- lse merge -------------------------------------------------
__global__ void lse_merge_kernel(int ntiles) {
    int m = blockIdx.x * 256 + threadIdx.x;
    if (m >= B_DIM) return;
    float M = -3.0e38f;
    for (int t = 0; t < ntiles; ++t) M = fmaxf(M, g_pm[(size_t)t * B_DIM + m]);
    float S = 0.f;
    for (int t = 0; t < ntiles; ++t) {
        float pm = g_pm[(size_t)t * B_DIM + m];
        if (pm > -1.0e38f) S += g_ps[(size_t)t * B_DIM + m] * fexp(pm - M);
    }
    g_L[m] = M + logf(S);
}

// -------------------- gemm2: part = exp(z-L) @ pat + colmax (fp16 1-pass) ------
// smem/stage: A[128][40] 10240 + B[32][264] 16896 = 27136; x2 = 54272
// epilogue overlay: float Cs[128][264] = 135168
#define SM2_BYTES 135168
__global__ __launch_bounds__(512) void gemm2_kernel(int Nn, int CHv) {
    extern __shared__ char sm[];
    const uint32_t sb = smem_u32(sm);
    float* Cs = (float*)sm;
    __shared__ unsigned scm[2][32];
    const int tid = threadIdx.x, wid = tid >> 5, lane = tid & 31;
    const int wm = wid >> 2, wd = wid & 3;              // 4 x 4 warps, tile 32 x 64
    const int m0 = blockIdx.x * 128;
    const int sp = blockIdx.y;
    const int ns = sp * CHv, ne = min(ns + CHv, Nn);
    if (ns >= ne) {
        const size_t pb = ((size_t)sp * B_DIM + m0) * D_DIM;
        for (int i = tid; i < 128 * D_DIM / 4; i += 512)
            *(float4*)&g_part[pb + (size_t)i * 4] = make_float4(0.f, 0.f, 0.f, 0.f);
        return;
    }
    const int nch = (ne - ns + 31) / 32;

    wmma::fragment<wmma::accumulator, 16, 16, 16, float> acc[2][4];
#pragma unroll
    for (int mi = 0; mi < 2; ++mi)
#pragma unroll
        for (int ni = 0; ni < 4; ++ni) wmma::fill_fragment(acc[mi][ni], 0.0f);

    const int r = tid >> 2, ng = (tid & 3) * 8;
    const float Lm = g_L[m0 + r];
    const float* zrow = g_z + (size_t)(m0 + r) * NPAD;
    const uint32_t dA = sb + r * 80 + ng * 2;
    if (tid < 32) { scm[0][tid] = 0u; scm[1][tid] = 0u; }
    __syncthreads();

#define G2_WCOMP(k0v, buf, chpar) do { \
        float e[8]; \
        long nbase = (long)(k0v) + ng; \
        if (nbase + 8 <= Nn) { \
            float4 a = *(const float4*)&zrow[nbase]; \
            float4 b = *(const float4*)&zrow[nbase + 4]; \
            e[0] = fexp(a.x - Lm); e[1] = fexp(a.y - Lm); \
            e[2] = fexp(a.z - Lm); e[3] = fexp(a.w - Lm); \
            e[4] = fexp(b.x - Lm); e[5] = fexp(b.y - Lm); \
            e[6] = fexp(b.z - Lm); e[7] = fexp(b.w - Lm); \
        } else { \
            for (int j = 0; j < 8; ++j) { \
                long nn = nbase + j; \
                e[j] = (nn < Nn) ? fexp(zrow[nn] - Lm) : 0.f; \
            } \
        } \
        uint32_t h0 = pk2h(e[0], e[1]), h1 = pk2h(e[2], e[3]); \
        uint32_t h2 = pk2h(e[4], e[5]), h3 = pk2h(e[6], e[7]); \
        uint32_t doff = dA + (buf) * 27136 - sb; \
        *(uint4*)(sm + doff) = make_uint4(h0, h1, h2, h3); \
        uint32_t cm[8]; \
        for (int j = 0; j < 8; ++j) cm[j] = __float_as_uint(e[j]); \
        for (int off = 4; off <= 16; off <<= 1) \
            for (int j = 0; j < 8; ++j) { \
                uint32_t o = __shfl_xor_sync(0xffffffffu, cm[j], off); \
                cm[j] = (o > cm[j]) ? o : cm[j]; \
            } \
        if ((lane >> 2) == 0) \
            for (int j = 0; j < 8; ++j) atomicMax(&scm[chpar][(lane & 3) * 8 + j], cm[j]); \
    } while (0)

#define G2_BISSUE(k0v, buf) do { \
        int s0 = tid, s1 = tid + 512; \
        uint32_t base = sb + (buf) * 27136 + 10240; \
        const char* psrc = (const char*)(g_patf + (size_t)(k0v) * D_DIM); \
        CP16(base + (s0 >> 5) * 528 + (s0 & 31) * 16, psrc + (s0 >> 5) * 512 + (s0 & 31) * 16); \
        CP16(base + (s1 >> 5) * 528 + (s1 & 31) * 16, psrc + (s1 >> 5) * 512 + (s1 & 31) * 16); \
        CP_COMMIT(); } while (0)

    G2_BISSUE(ns, 0);
    G2_WCOMP(ns, 0, 0);
    CP_WAIT0();
    __syncthreads();

    for (int ci = 0; ci < nch; ++ci) {
        const int cur = ci & 1;
        if (ci > 0 && tid < 32) {
            int n = ns + (ci - 1) * 32 + tid;
            unsigned v = scm[cur ^ 1][tid];
            if (n < Nn && v) atomicMax(&g_cmax[n], v);
            scm[cur ^ 1][tid] = 0u;
        }
        const bool pre = (ci + 1 < nch);
        if (pre) G2_BISSUE(ns + (ci + 1) * 32, cur ^ 1);

        const __half* Ah = (const __half*)(sm + cur * 27136);
        const __half* Bs = (const __half*)(sm + cur * 27136 + 10240);
#pragma unroll
        for (int kk = 0; kk < 32; kk += 16) {
            wmma::fragment<wmma::matrix_a, 16, 16, 16, __half, wmma::row_major> ah[2];
            wmma::fragment<wmma::matrix_b, 16, 16, 16, __half, wmma::row_major> bh[4];
#pragma unroll
            for (int mi = 0; mi < 2; ++mi)
                wmma::load_matrix_sync(ah[mi], &Ah[(wm * 32 + mi * 16) * 40 + kk], 40);
#pragma unroll
            for (int ni = 0; ni < 4; ++ni)
                wmma::load_matrix_sync(bh[ni], &Bs[kk * 264 + wd * 64 + ni * 16], 264);
#pragma unroll
            for (int mi = 0; mi < 2; ++mi)
#pragma unroll
                for (int ni = 0; ni < 4; ++ni)
                    wmma::mma_sync(acc[mi][ni], ah[mi], bh[ni], acc[mi][ni]);
        }
        if (pre) {
            G2_WCOMP(ns + (ci + 1) * 32, cur ^ 1, cur ^ 1);
            CP_WAIT0();
        }
        __syncthreads();
    }
    if (tid < 32) {
        int n = ns + (nch - 1) * 32 + tid;
        unsigned v = scm[(nch - 1) & 1][tid];
        if (n < Nn && v) atomicMax(&g_cmax[n], v);
    }

#pragma unroll
    for (int mi = 0; mi < 2; ++mi)
#pragma unroll
        for (int ni = 0; ni < 4; ++ni)
            wmma::store_matrix_sync(&Cs[(wm * 32 + mi * 16) * 264 + wd * 64 + ni * 16],
                                    acc[mi][ni], 264, wmma::mem_row_major);
    __syncthreads();
    const int rr = tid >> 2, cgr = (tid & 3) * 64;
    const size_t ob = ((size_t)sp * B_DIM + m0 + rr) * D_DIM + cgr;
#pragma unroll
    for (int j = 0; j < 64; j += 4)
        *(float4*)&g_part[ob + j] = *(const float4*)&Cs[rr * 264 + cgr + j];
}

// -------------------- reductions / output --------------------------------------
__global__ void reduce_ret_kernel(float* __restrict__ out) {
    size_t i = (size_t)blockIdx.x * 256 + threadIdx.x;
    float4 s = make_float4(0.f, 0.f, 0.f, 0.f);
    for (int sp = 0; sp < NSPLIT; ++sp) {
        float4 v = *(const float4*)&g_part[(size_t)sp * (B_DIM * D_DIM) + i * 4];
        s.x += v.x; s.y += v.y; s.z += v.z; s.w += v.w;
    }
    *(float4*)&out[i * 4] = s;
}

__global__ void depths_kernel(const float* __restrict__ depths,
                              float* __restrict__ out, int Nn) {
    int i = blockIdx.x * 256 + threadIdx.x;
    if (i >= Nn) return;
    float d = depths[i];
    float maxw = __uint_as_float(g_cmax[i]);
    float dom = log1pf(d) / fmaxf(__int_as_float(g_logdmax), 1e-8f);
    float rate = 0.01f * (1.0f - 0.7f * dom);
    out[B_DIM * D_DIM + i] = d + ((maxw > 0.1f) ? rate * maxw : 0.0f);
}

extern "C" void kernel_launch(void* const* d_in, const int* in_sizes, int n_in,
                              void* d_out, int out_size) {
    const float* state  = (const float*)d_in[0];
    const float* W      = (const float*)d_in[1];
    const float* pat    = (const float*)d_in[2];
    const float* depths = (const float*)d_in[3];
    const float* gate   = (const float*)d_in[4];
    float* out = (float*)d_out;
    const int Nn = in_sizes[3];

    cudaFuncSetAttribute(gemm1_kernel, cudaFuncAttributeMaxDynamicSharedMemorySize, SM1_BYTES);
    cudaFuncSetAttribute(gemm2_kernel, cudaFuncAttributeMaxDynamicSharedMemorySize, SM2_BYTES);

    const int nbN = (Nn + 255) / 256;
    init_kernel<<<nbN, 256>>>(Nn);
    proj_kernel<<<B_DIM, 256>>>(state, W);
    bias_kernel<<<nbN, 256>>>(depths, gate, Nn);
    patprep_kernel<<<(NPAD * D_DIM / 4) / 256, 256>>>(pat, Nn);

    gemm1_kernel<<<dim3(B_DIM / 128, NT1), 512, SM1_BYTES>>>(Nn);
    lse_merge_kernel<<<B_DIM / 256, 256>>>(NT1);

    const int CHv = ((Nn + NSPLIT * 32 - 1) / (NSPLIT * 32)) * 32;
    gemm2_kernel<<<dim3(B_DIM / 128, NSPLIT), 512, SM2_BYTES>>>(Nn, CHv);

    reduce_ret_kernel<<<(B_DIM * D_DIM / 4) / 256, 256>>>(out);
    depths_kernel<<<nbN, 256>>>(depths, out, Nn);
}